// round 6
// baseline (speedup 1.0000x reference)
#include <cuda_runtime.h>
#include <math.h>

#define NXX   512
#define NWW   512
#define NYY   256
#define NWUP  128
#define NB    1024
#define NHR   32
#define TT    (NWUP + 1 + NHR)          // 161

#define BSTEP    ((size_t)NB * NXX)     // 524,288
#define X_SIZE   ((size_t)TT * NB * NXX)
#define L_OFF    (X_SIZE)
#define L_SIZE   ((size_t)NWUP * NB * NWW)
#define Y_OFF    (L_OFF + L_SIZE)

__device__ __forceinline__ float sigm(float x) { return 1.0f / (1.0f + expf(-x)); }

// JAX partitionable threefry bits: counter (0, i), key (0,1), bits = x0 ^ x1.
// sign = -1 if top bit set (u >= 0.5), else +1.
__device__ __forceinline__ float frand_sign(unsigned i) {
    const unsigned ks0 = 0u, ks1 = 1u, ks2 = 0x1BD11BDBu;
    unsigned x0 = 0u + ks0;
    unsigned x1 = i  + ks1;
#define QR4(RA,RB,RC,RD) \
    x0 += x1; x1 = __funnelshift_l(x1, x1, RA); x1 ^= x0; \
    x0 += x1; x1 = __funnelshift_l(x1, x1, RB); x1 ^= x0; \
    x0 += x1; x1 = __funnelshift_l(x1, x1, RC); x1 ^= x0; \
    x0 += x1; x1 = __funnelshift_l(x1, x1, RD); x1 ^= x0;
    QR4(13,15,26, 6)  x0 += ks1; x1 += ks2 + 1u;
    QR4(17,29,16,24)  x0 += ks2; x1 += ks0 + 2u;
    QR4(13,15,26, 6)  x0 += ks0; x1 += ks1 + 3u;
    QR4(17,29,16,24)  x0 += ks1; x1 += ks2 + 4u;
    QR4(13,15,26, 6)  x0 += ks2; x1 += ks0 + 5u;
#undef QR4
    return ((x0 ^ x1) & 0x80000000u) ? -1.0f : 1.0f;
}

// dot over K=512 from smem S (layout [r][512]) against W row; acc[8] +=
__device__ __forceinline__ void dot512(float acc[8], const float* __restrict__ Wrow,
                                       const float* __restrict__ S) {
#pragma unroll 8
    for (int k = 0; k < 512; k += 4) {
        float4 wv = *(const float4*)(Wrow + k);
#pragma unroll
        for (int r = 0; r < 8; r++) {
            float4 hv = *(const float4*)(S + r * 512 + k);
            acc[r] = fmaf(wv.x, hv.x, acc[r]);
            acc[r] = fmaf(wv.y, hv.y, acc[r]);
            acc[r] = fmaf(wv.z, hv.z, acc[r]);
            acc[r] = fmaf(wv.w, hv.w, acc[r]);
        }
    }
}

// ---------------------------------------------------------------------------
// Persistent recurrence (includes x0). 128 CTAs x 512 threads, 8 rows/CTA.
// Thread tid owns output column o = tid (plus o+512, o+1024 for GRU gates).
// ---------------------------------------------------------------------------
__global__ void __launch_bounds__(512) recur_kernel(
    const float* __restrict__ Y0,
    const float* __restrict__ Wq,  const float* __restrict__ bq,
    const float* __restrict__ Wl1, const float* __restrict__ bl1,
    const float* __restrict__ Wl2, const float* __restrict__ bl2,
    const float* __restrict__ Wih, const float* __restrict__ Whh,
    const float* __restrict__ bih, const float* __restrict__ bhh,
    float* __restrict__ out)
{
    __shared__ float hA[8 * 512];
    __shared__ float hB[8 * 512];
    __shared__ float ybuf[8 * 256];
    __shared__ float l1buf[8 * 512];
    __shared__ float wbuf[8 * 512];

    const int tid = threadIdx.x;
    const int rowBase = blockIdx.x * 8;
    float* hc = hA;
    float* hn = hB;

    // ---- x0 = tanh(Y0[0] @ Wq.T + bq) ----
    for (int i = tid; i < 8 * 256; i += 512)
        ybuf[i] = Y0[(size_t)(rowBase + (i >> 8)) * NYY + (i & 255)];
    __syncthreads();
    {
        float acc[8] = {0,0,0,0,0,0,0,0};
        const float* wr = Wq + (size_t)tid * NYY;
#pragma unroll 8
        for (int k = 0; k < 256; k += 4) {
            float4 wv = *(const float4*)(wr + k);
#pragma unroll
            for (int r = 0; r < 8; r++) {
                float4 yv = *(const float4*)(ybuf + r * 256 + k);
                acc[r] = fmaf(wv.x, yv.x, acc[r]);
                acc[r] = fmaf(wv.y, yv.y, acc[r]);
                acc[r] = fmaf(wv.z, yv.z, acc[r]);
                acc[r] = fmaf(wv.w, yv.w, acc[r]);
            }
        }
        const float b = bq[tid];
#pragma unroll
        for (int r = 0; r < 8; r++) {
            float v = tanhf(acc[r] + b);
            hc[r * 512 + tid] = v;
            out[(size_t)(rowBase + r) * NXX + tid] = v;
        }
    }
    __syncthreads();

    // ---- 160 sequential steps ----
    for (int t = 0; t < NWUP + NHR; t++) {
        if (t < NWUP) {
            // y = Y0[t+1]
            for (int i = tid; i < 8 * 256; i += 512)
                ybuf[i] = Y0[((size_t)(t + 1) * NB + rowBase + (i >> 8)) * NYY + (i & 255)];
            __syncthreads();

            // l1 = tanh([h | y] @ Wl1.T + bl1)   (Wl1 row: 512 h-weights, 256 y-weights)
            {
                float acc[8] = {0,0,0,0,0,0,0,0};
                const float* wr = Wl1 + (size_t)tid * (NXX + NYY);
                dot512(acc, wr, hc);
#pragma unroll 8
                for (int k = 0; k < 256; k += 4) {
                    float4 wv = *(const float4*)(wr + 512 + k);
#pragma unroll
                    for (int r = 0; r < 8; r++) {
                        float4 yv = *(const float4*)(ybuf + r * 256 + k);
                        acc[r] = fmaf(wv.x, yv.x, acc[r]);
                        acc[r] = fmaf(wv.y, yv.y, acc[r]);
                        acc[r] = fmaf(wv.z, yv.z, acc[r]);
                        acc[r] = fmaf(wv.w, yv.w, acc[r]);
                    }
                }
                const float b = bl1[tid];
#pragma unroll
                for (int r = 0; r < 8; r++)
                    l1buf[r * 512 + tid] = tanhf(acc[r] + b);
            }
            __syncthreads();

            // logit = l1 @ Wl2.T + bl2 ; write logit_Q_w[t] ; w = tanh(0.5*logit)
            {
                float acc[8] = {0,0,0,0,0,0,0,0};
                dot512(acc, Wl2 + (size_t)tid * 512, l1buf);
                const float b = bl2[tid];
#pragma unroll
                for (int r = 0; r < 8; r++) {
                    float lg = acc[r] + b;
                    out[L_OFF + ((size_t)t * NB + rowBase + r) * NWW + tid] = lg;
                    wbuf[r * 512 + tid] = tanhf(0.5f * lg);
                }
            }
            __syncthreads();
        } else {
            // free-run: w = +/-1 from threefry
            const unsigned tf = (unsigned)(t - NWUP);
            for (int i = tid; i < 8 * 512; i += 512) {
                const int r = i >> 9, j = i & 511;
                const unsigned idx = ((tf * NB + (unsigned)(rowBase + r)) << 9) + (unsigned)j;
                wbuf[i] = frand_sign(idx);
            }
            __syncthreads();
        }

        // ---- GRU cell: thread tid handles column j = tid for all 3 gates ----
        float rg[8], zg[8];
        {   // r gate: rows [0,512)
            float gi[8] = {0,0,0,0,0,0,0,0}, gh[8] = {0,0,0,0,0,0,0,0};
            dot512(gi, Wih + (size_t)tid * 512, wbuf);
            dot512(gh, Whh + (size_t)tid * 512, hc);
            const float b = bih[tid] + bhh[tid];
#pragma unroll
            for (int r = 0; r < 8; r++) rg[r] = sigm(gi[r] + gh[r] + b);
        }
        {   // z gate: rows [512,1024)
            const int o = tid + 512;
            float gi[8] = {0,0,0,0,0,0,0,0}, gh[8] = {0,0,0,0,0,0,0,0};
            dot512(gi, Wih + (size_t)o * 512, wbuf);
            dot512(gh, Whh + (size_t)o * 512, hc);
            const float b = bih[o] + bhh[o];
#pragma unroll
            for (int r = 0; r < 8; r++) zg[r] = sigm(gi[r] + gh[r] + b);
        }
        {   // n gate: rows [1024,1536); h' = (1-z)*n + z*h
            const int o = tid + 1024;
            float gi[8] = {0,0,0,0,0,0,0,0}, gh[8] = {0,0,0,0,0,0,0,0};
            dot512(gi, Wih + (size_t)o * 512, wbuf);
            dot512(gh, Whh + (size_t)o * 512, hc);
            const float bi = bih[o], bh = bhh[o];
#pragma unroll
            for (int r = 0; r < 8; r++) {
                const float nn = tanhf(gi[r] + bi + rg[r] * (gh[r] + bh));
                const float ho = hc[r * 512 + tid];
                const float hv = (1.0f - zg[r]) * nn + zg[r] * ho;
                hn[r * 512 + tid] = hv;
                out[((size_t)(t + 1) * NB + rowBase + r) * NXX + tid] = hv;
            }
        }
        __syncthreads();
        float* tmp = hc; hc = hn; hn = tmp;
    }
}

// ---------------------------------------------------------------------------
// Yhat = tanh(X @ Wp1.T + bp1) @ Wp2.T + bp2   (8 rows per CTA, 512 threads)
// ---------------------------------------------------------------------------
__global__ void __launch_bounds__(512) proj_kernel(
    const float* __restrict__ Wp1, const float* __restrict__ bp1,
    const float* __restrict__ Wp2, const float* __restrict__ bp2,
    float* __restrict__ out)
{
    __shared__ float sx[8 * 512];
    __shared__ float st[8 * 512];
    const int tid = threadIdx.x;
    const size_t rowBase = (size_t)blockIdx.x * 8;

    for (int i = tid; i < 8 * 512; i += 512)
        sx[i] = out[(rowBase + (i >> 9)) * NXX + (i & 511)];
    __syncthreads();

    {   // layer 1: o = tid, 512 outputs
        float acc[8] = {0,0,0,0,0,0,0,0};
        dot512(acc, Wp1 + (size_t)tid * NXX, sx);
        const float b = bp1[tid];
#pragma unroll
        for (int r = 0; r < 8; r++)
            st[r * 512 + tid] = tanhf(acc[r] + b);
    }
    __syncthreads();

    {   // layer 2: 256 outputs; threads split into two row-halves
        const int o = tid & 255;
        const int rh = tid >> 8;          // 0 -> rows 0..3, 1 -> rows 4..7
        float acc[4] = {0,0,0,0};
        const float* wr = Wp2 + (size_t)o * NXX;
#pragma unroll 8
        for (int k = 0; k < 512; k += 4) {
            float4 wv = *(const float4*)(wr + k);
#pragma unroll
            for (int r = 0; r < 4; r++) {
                float4 hv = *(const float4*)(st + (rh * 4 + r) * 512 + k);
                acc[r] = fmaf(wv.x, hv.x, acc[r]);
                acc[r] = fmaf(wv.y, hv.y, acc[r]);
                acc[r] = fmaf(wv.z, hv.z, acc[r]);
                acc[r] = fmaf(wv.w, hv.w, acc[r]);
            }
        }
        const float b = bp2[o];
#pragma unroll
        for (int r = 0; r < 4; r++)
            out[Y_OFF + (rowBase + rh * 4 + r) * NYY + o] = acc[r] + b;
    }
}

extern "C" void kernel_launch(void* const* d_in, const int* in_sizes, int n_in,
                              void* d_out, int out_size) {
    // dict/signature order: Y0, [Nhrzn,] Wq,bq, Wp1,bp1, Wp2,bp2,
    //                       Wl1,bl1, Wl2,bl2, W_ih,W_hh, b_ih,b_hh
    int off = (n_in >= 16 && in_sizes[1] == 1) ? 2 : 1;
    const float* Y0  = (const float*)d_in[0];
    const float* Wq  = (const float*)d_in[off + 0];
    const float* bq  = (const float*)d_in[off + 1];
    const float* Wp1 = (const float*)d_in[off + 2];
    const float* bp1 = (const float*)d_in[off + 3];
    const float* Wp2 = (const float*)d_in[off + 4];
    const float* bp2 = (const float*)d_in[off + 5];
    const float* Wl1 = (const float*)d_in[off + 6];
    const float* bl1 = (const float*)d_in[off + 7];
    const float* Wl2 = (const float*)d_in[off + 8];
    const float* bl2 = (const float*)d_in[off + 9];
    const float* Wih = (const float*)d_in[off + 10];
    const float* Whh = (const float*)d_in[off + 11];
    const float* bih = (const float*)d_in[off + 12];
    const float* bhh = (const float*)d_in[off + 13];
    float* out = (float*)d_out;

    recur_kernel<<<NB / 8, 512>>>(Y0, Wq, bq, Wl1, bl1, Wl2, bl2,
                                  Wih, Whh, bih, bhh, out);
    proj_kernel<<<(TT * NB) / 8, 512>>>(Wp1, bp1, Wp2, bp2, out);
}

// round 7
// speedup vs baseline: 1.3276x; 1.3276x over previous
#include <cuda_runtime.h>
#include <math.h>

#define NXX   512
#define NWW   512
#define NYY   256
#define NWUP  128
#define NB    1024
#define NHR   32
#define TT    (NWUP + 1 + NHR)          // 161

#define X_SIZE   ((size_t)TT * NB * NXX)
#define L_OFF    (X_SIZE)
#define L_SIZE   ((size_t)NWUP * NB * NWW)
#define Y_OFF    (L_OFF + L_SIZE)

__device__ __forceinline__ float sigm(float x) { return 1.0f / (1.0f + expf(-x)); }

// JAX partitionable threefry bits: counter (0, i), key (0,1), bits = x0 ^ x1.
__device__ __forceinline__ float frand_sign(unsigned i) {
    const unsigned ks0 = 0u, ks1 = 1u, ks2 = 0x1BD11BDBu;
    unsigned x0 = 0u + ks0;
    unsigned x1 = i  + ks1;
#define QR4(RA,RB,RC,RD) \
    x0 += x1; x1 = __funnelshift_l(x1, x1, RA); x1 ^= x0; \
    x0 += x1; x1 = __funnelshift_l(x1, x1, RB); x1 ^= x0; \
    x0 += x1; x1 = __funnelshift_l(x1, x1, RC); x1 ^= x0; \
    x0 += x1; x1 = __funnelshift_l(x1, x1, RD); x1 ^= x0;
    QR4(13,15,26, 6)  x0 += ks1; x1 += ks2 + 1u;
    QR4(17,29,16,24)  x0 += ks2; x1 += ks0 + 2u;
    QR4(13,15,26, 6)  x0 += ks0; x1 += ks1 + 3u;
    QR4(17,29,16,24)  x0 += ks1; x1 += ks2 + 4u;
    QR4(13,15,26, 6)  x0 += ks2; x1 += ks0 + 5u;
#undef QR4
    return ((x0 ^ x1) & 0x80000000u) ? -1.0f : 1.0f;
}

// ---------------------------------------------------------------------------
// Scheme B warp micro-GEMM: lane = c*8 + k8 (c = col-in-group 0..3, k8 = k-slice).
// Lane accumulates k in {32j + 4*k8 .. +3}; octet (fixed c) covers 128B of the
// weight row per j -> fully-coalesced LDG.128 (4 lines/instr, 100% utilization).
// After redB (xor 1,2,4 within octet) every lane holds full dots for all rows.
// ---------------------------------------------------------------------------
template<int NR, int KLEN, int STRIDE>
__device__ __forceinline__ void dotB(float* acc, const float* __restrict__ Wrow,
                                     const float* __restrict__ S, int k8) {
    const int kb = 4 * k8;
#pragma unroll 4
    for (int j = 0; j < KLEN / 32; j++) {
        float4 wv = *(const float4*)(Wrow + 32 * j + kb);
#pragma unroll
        for (int r = 0; r < NR; r++) {
            float4 sv = *(const float4*)(S + r * STRIDE + 32 * j + kb);
            acc[r] = fmaf(wv.x, sv.x, acc[r]);
            acc[r] = fmaf(wv.y, sv.y, acc[r]);
            acc[r] = fmaf(wv.z, sv.z, acc[r]);
            acc[r] = fmaf(wv.w, sv.w, acc[r]);
        }
    }
}
template<int NR>
__device__ __forceinline__ void redB(float* acc) {
#pragma unroll
    for (int r = 0; r < NR; r++) {
        acc[r] += __shfl_xor_sync(0xffffffffu, acc[r], 1);
        acc[r] += __shfl_xor_sync(0xffffffffu, acc[r], 2);
        acc[r] += __shfl_xor_sync(0xffffffffu, acc[r], 4);
    }
}
#define ZA(a, n) float a[n]; _Pragma("unroll") for (int _z = 0; _z < n; _z++) a[_z] = 0.0f;

// ---------------------------------------------------------------------------
// Persistent recurrence (incl. x0). 128 CTAs x 512 threads, 8 rows/CTA.
// ---------------------------------------------------------------------------
__global__ void __launch_bounds__(512) recur_kernel(
    const float* __restrict__ Y0,
    const float* __restrict__ Wq,  const float* __restrict__ bq,
    const float* __restrict__ Wl1, const float* __restrict__ bl1,
    const float* __restrict__ Wl2, const float* __restrict__ bl2,
    const float* __restrict__ Wih, const float* __restrict__ Whh,
    const float* __restrict__ bih, const float* __restrict__ bhh,
    float* __restrict__ out)
{
    __shared__ float hA[8 * 512];
    __shared__ float hB[8 * 512];
    __shared__ float ybuf[8 * 256];
    __shared__ float l1buf[8 * 512];
    __shared__ float wbuf[8 * 512];

    const int tid = threadIdx.x;
    const int warp = tid >> 5, lane = tid & 31;
    const int k8 = lane & 7, c = lane >> 3;
    const int rowBase = blockIdx.x * 8;
    float* hc = hA;
    float* hn = hB;

    // ---- x0 = tanh(Y0[0] @ Wq.T + bq) ----
    for (int i = tid; i < 8 * 256; i += 512)
        ybuf[i] = Y0[(size_t)(rowBase + (i >> 8)) * NYY + (i & 255)];
    __syncthreads();
    for (int g = warp; g < 128; g += 16) {
        const int o = g * 4 + c;
        ZA(acc, 8);
        dotB<8, 256, 256>(acc, Wq + (size_t)o * NYY, ybuf, k8);
        redB<8>(acc);
        const float v = tanhf(acc[k8] + bq[o]);
        hc[k8 * 512 + o] = v;
        out[(size_t)(rowBase + k8) * NXX + o] = v;
    }
    __syncthreads();

    // ---- 160 sequential steps ----
    for (int t = 0; t < NWUP + NHR; t++) {
        if (t < NWUP) {
            for (int i = tid; i < 8 * 256; i += 512)
                ybuf[i] = Y0[((size_t)(t + 1) * NB + rowBase + (i >> 8)) * NYY + (i & 255)];
            __syncthreads();

            // l1 = tanh([h | y] @ Wl1.T + bl1)
            for (int g = warp; g < 128; g += 16) {
                const int o = g * 4 + c;
                ZA(acc, 8);
                const float* wr = Wl1 + (size_t)o * (NXX + NYY);
                dotB<8, 512, 512>(acc, wr, hc, k8);
                dotB<8, 256, 256>(acc, wr + 512, ybuf, k8);
                redB<8>(acc);
                l1buf[k8 * 512 + o] = tanhf(acc[k8] + bl1[o]);
            }
            __syncthreads();

            // logit = l1 @ Wl2.T + bl2 -> out ; w = tanh(0.5*logit)
            for (int g = warp; g < 128; g += 16) {
                const int o = g * 4 + c;
                ZA(acc, 8);
                dotB<8, 512, 512>(acc, Wl2 + (size_t)o * 512, l1buf, k8);
                redB<8>(acc);
                const float lg = acc[k8] + bl2[o];
                out[L_OFF + ((size_t)t * NB + rowBase + k8) * NWW + o] = lg;
                wbuf[k8 * 512 + o] = tanhf(0.5f * lg);
            }
            __syncthreads();
        } else {
            const unsigned tf = (unsigned)(t - NWUP);
            for (int i = tid; i < 8 * 512; i += 512) {
                const int r = i >> 9, j = i & 511;
                const unsigned idx = ((tf * NB + (unsigned)(rowBase + r)) << 9) + (unsigned)j;
                wbuf[i] = frand_sign(idx);
            }
            __syncthreads();
        }

        // ---- GRU: lane (c,k8) computes r,z,n for (row=k8, col=o) in registers ----
        for (int g = warp; g < 128; g += 16) {
            const int o = g * 4 + c;
            float rv, zv;
            {
                ZA(ai, 8); ZA(ah, 8);
                dotB<8, 512, 512>(ai, Wih + (size_t)o * 512, wbuf, k8);
                dotB<8, 512, 512>(ah, Whh + (size_t)o * 512, hc, k8);
                redB<8>(ai); redB<8>(ah);
                rv = sigm(ai[k8] + ah[k8] + bih[o] + bhh[o]);
            }
            {
                const int o2 = o + 512;
                ZA(ai, 8); ZA(ah, 8);
                dotB<8, 512, 512>(ai, Wih + (size_t)o2 * 512, wbuf, k8);
                dotB<8, 512, 512>(ah, Whh + (size_t)o2 * 512, hc, k8);
                redB<8>(ai); redB<8>(ah);
                zv = sigm(ai[k8] + ah[k8] + bih[o2] + bhh[o2]);
            }
            {
                const int o3 = o + 1024;
                ZA(ai, 8); ZA(ah, 8);
                dotB<8, 512, 512>(ai, Wih + (size_t)o3 * 512, wbuf, k8);
                dotB<8, 512, 512>(ah, Whh + (size_t)o3 * 512, hc, k8);
                redB<8>(ai); redB<8>(ah);
                const float nv = tanhf(ai[k8] + bih[o3] + rv * (ah[k8] + bhh[o3]));
                const float ho = hc[k8 * 512 + o];
                const float hv = (1.0f - zv) * nv + zv * ho;
                hn[k8 * 512 + o] = hv;
                out[((size_t)(t + 1) * NB + rowBase + k8) * NXX + o] = hv;
            }
        }
        __syncthreads();
        float* tmp = hc; hc = hn; hn = tmp;
    }
}

// ---------------------------------------------------------------------------
// Yhat = tanh(X @ Wp1.T + bp1) @ Wp2.T + bp2   (16 rows per CTA, 512 threads)
// ---------------------------------------------------------------------------
__global__ void __launch_bounds__(512) proj_kernel(
    const float* __restrict__ Wp1, const float* __restrict__ bp1,
    const float* __restrict__ Wp2, const float* __restrict__ bp2,
    float* __restrict__ out)
{
    __shared__ float sx[16 * 512];
    __shared__ float st[16 * 512];
    const int tid = threadIdx.x;
    const int warp = tid >> 5, lane = tid & 31;
    const int k8 = lane & 7, c = lane >> 3;
    const size_t rowBase = (size_t)blockIdx.x * 16;

    for (int i = tid; i < 16 * 512; i += 512)
        sx[i] = out[(rowBase + (i >> 9)) * NXX + (i & 511)];
    __syncthreads();

    for (int g = warp; g < 128; g += 16) {
        const int o = g * 4 + c;
        ZA(acc, 16);
        dotB<16, 512, 512>(acc, Wp1 + (size_t)o * NXX, sx, k8);
        redB<16>(acc);
        const float b = bp1[o];
        st[k8 * 512 + o]       = tanhf(acc[k8] + b);
        st[(k8 + 8) * 512 + o] = tanhf(acc[k8 + 8] + b);
    }
    __syncthreads();

    for (int g = warp; g < 64; g += 16) {
        const int o = g * 4 + c;
        ZA(acc, 16);
        dotB<16, 512, 512>(acc, Wp2 + (size_t)o * NXX, st, k8);
        redB<16>(acc);
        const float b = bp2[o];
        out[Y_OFF + (rowBase + k8) * NYY + o]       = acc[k8] + b;
        out[Y_OFF + (rowBase + k8 + 8) * NYY + o]   = acc[k8 + 8] + b;
    }
}

extern "C" void kernel_launch(void* const* d_in, const int* in_sizes, int n_in,
                              void* d_out, int out_size) {
    // dict/signature order: Y0, [Nhrzn,] Wq,bq, Wp1,bp1, Wp2,bp2,
    //                       Wl1,bl1, Wl2,bl2, W_ih,W_hh, b_ih,b_hh
    int off = (n_in >= 16 && in_sizes[1] == 1) ? 2 : 1;
    const float* Y0  = (const float*)d_in[0];
    const float* Wq  = (const float*)d_in[off + 0];
    const float* bq  = (const float*)d_in[off + 1];
    const float* Wp1 = (const float*)d_in[off + 2];
    const float* bp1 = (const float*)d_in[off + 3];
    const float* Wp2 = (const float*)d_in[off + 4];
    const float* bp2 = (const float*)d_in[off + 5];
    const float* Wl1 = (const float*)d_in[off + 6];
    const float* bl1 = (const float*)d_in[off + 7];
    const float* Wl2 = (const float*)d_in[off + 8];
    const float* bl2 = (const float*)d_in[off + 9];
    const float* Wih = (const float*)d_in[off + 10];
    const float* Whh = (const float*)d_in[off + 11];
    const float* bih = (const float*)d_in[off + 12];
    const float* bhh = (const float*)d_in[off + 13];
    float* out = (float*)d_out;

    recur_kernel<<<NB / 8, 512>>>(Y0, Wq, bq, Wl1, bl1, Wl2, bl2,
                                  Wih, Whh, bih, bhh, out);
    proj_kernel<<<(TT * NB) / 16, 512>>>(Wp1, bp1, Wp2, bp2, out);
}

// round 9
// speedup vs baseline: 2.3336x; 1.7577x over previous
#include <cuda_runtime.h>
#include <math.h>

#define NXX   512
#define NWW   512
#define NYY   256
#define NWUP  128
#define NB    1024
#define NHR   32
#define TT    (NWUP + 1 + NHR)          // 161

#define X_SIZE   ((size_t)TT * NB * NXX)
#define L_OFF    (X_SIZE)
#define L_SIZE   ((size_t)NWUP * NB * NWW)
#define Y_OFF    (L_OFF + L_SIZE)

__device__ __forceinline__ float sigm(float x) { return 1.0f / (1.0f + expf(-x)); }

// JAX partitionable threefry bits: counter (0, i), key (0,1), bits = x0 ^ x1.
__device__ __forceinline__ float frand_sign(unsigned i) {
    const unsigned ks0 = 0u, ks1 = 1u, ks2 = 0x1BD11BDBu;
    unsigned x0 = 0u + ks0;
    unsigned x1 = i  + ks1;
#define QR4(RA,RB,RC,RD) \
    x0 += x1; x1 = __funnelshift_l(x1, x1, RA); x1 ^= x0; \
    x0 += x1; x1 = __funnelshift_l(x1, x1, RB); x1 ^= x0; \
    x0 += x1; x1 = __funnelshift_l(x1, x1, RC); x1 ^= x0; \
    x0 += x1; x1 = __funnelshift_l(x1, x1, RD); x1 ^= x0;
    QR4(13,15,26, 6)  x0 += ks1; x1 += ks2 + 1u;
    QR4(17,29,16,24)  x0 += ks2; x1 += ks0 + 2u;
    QR4(13,15,26, 6)  x0 += ks0; x1 += ks1 + 3u;
    QR4(17,29,16,24)  x0 += ks1; x1 += ks2 + 4u;
    QR4(13,15,26, 6)  x0 += ks2; x1 += ks0 + 5u;
#undef QR4
    return ((x0 ^ x1) & 0x80000000u) ? -1.0f : 1.0f;
}

// fma of two float4s into scalar accumulator (function, not macro: no token
// collision between parameter names and float4 fields)
__device__ __forceinline__ void fma4(float& a, const float4& u, const float4& v) {
    a = fmaf(u.x, v.x, a);
    a = fmaf(u.y, v.y, a);
    a = fmaf(u.z, v.z, a);
    a = fmaf(u.w, v.w, a);
}

// lane = c*8 + k8 ; octet (fixed c) covers 128B of a weight row per j-step.
template<int NR, int KLEN, int STRIDE>
__device__ __forceinline__ void dotB(float* acc, const float* __restrict__ Wrow,
                                     const float* __restrict__ S, int k8) {
    const int kb = 4 * k8;
#pragma unroll 4
    for (int j = 0; j < KLEN / 32; j++) {
        float4 wv = *(const float4*)(Wrow + 32 * j + kb);
#pragma unroll
        for (int r = 0; r < NR; r++) {
            float4 sv = *(const float4*)(S + r * STRIDE + 32 * j + kb);
            fma4(acc[r], wv, sv);
        }
    }
}

// 2-output-column dot: one smem read feeds 2 weight rows (halves LDS per FMA)
template<int NR, int KLEN, int STRIDE>
__device__ __forceinline__ void dot2(float* a0, float* a1,
                                     const float* __restrict__ W0,
                                     const float* __restrict__ W1,
                                     const float* __restrict__ S, int k8) {
    const int kb = 4 * k8;
#pragma unroll 4
    for (int j = 0; j < KLEN / 32; j++) {
        const int ko = 32 * j + kb;
        float4 w0 = *(const float4*)(W0 + ko);
        float4 w1 = *(const float4*)(W1 + ko);
#pragma unroll
        for (int r = 0; r < NR; r++) {
            float4 sv = *(const float4*)(S + r * STRIDE + ko);
            fma4(a0[r], w0, sv);
            fma4(a1[r], w1, sv);
        }
    }
}

template<int NR>
__device__ __forceinline__ void redB(float* acc) {
#pragma unroll
    for (int r = 0; r < NR; r++) {
        acc[r] += __shfl_xor_sync(0xffffffffu, acc[r], 1);
        acc[r] += __shfl_xor_sync(0xffffffffu, acc[r], 2);
        acc[r] += __shfl_xor_sync(0xffffffffu, acc[r], 4);
    }
}
#define ZA(a, n) float a[n]; _Pragma("unroll") for (int _z = 0; _z < n; _z++) a[_z] = 0.0f;

// ---------------------------------------------------------------------------
// Persistent recurrence (incl. x0). 128 CTAs x 512 threads, 8 rows/CTA.
// ---------------------------------------------------------------------------
__global__ void __launch_bounds__(512) recur_kernel(
    const float* __restrict__ Y0,
    const float* __restrict__ Wq,  const float* __restrict__ bq,
    const float* __restrict__ Wl1, const float* __restrict__ bl1,
    const float* __restrict__ Wl2, const float* __restrict__ bl2,
    const float* __restrict__ Wih, const float* __restrict__ Whh,
    const float* __restrict__ bih, const float* __restrict__ bhh,
    float* __restrict__ out)
{
    __shared__ float hA[8 * 512];
    __shared__ float hB[8 * 512];
    __shared__ float ybuf[8 * 256];
    __shared__ float l1buf[8 * 512];
    __shared__ float wbuf[8 * 512];

    const int tid = threadIdx.x;
    const int warp = tid >> 5, lane = tid & 31;
    const int k8 = lane & 7, c = lane >> 3;
    const int rowBase = blockIdx.x * 8;
    float* hc = hA;
    float* hn = hB;

    // ---- x0 = tanh(Y0[0] @ Wq.T + bq) ----
    for (int i = tid; i < 8 * 256; i += 512)
        ybuf[i] = Y0[(size_t)(rowBase + (i >> 8)) * NYY + (i & 255)];
    __syncthreads();
    for (int g = warp; g < 128; g += 16) {
        const int o = g * 4 + c;
        ZA(acc, 8);
        dotB<8, 256, 256>(acc, Wq + (size_t)o * NYY, ybuf, k8);
        redB<8>(acc);
        const float v = tanhf(acc[k8] + bq[o]);
        hc[k8 * 512 + o] = v;
        out[(size_t)(rowBase + k8) * NXX + o] = v;
    }
    __syncthreads();

    // ---- 160 sequential steps ----
    for (int t = 0; t < NWUP + NHR; t++) {
        if (t < NWUP) {
            for (int i = tid; i < 8 * 256; i += 512)
                ybuf[i] = Y0[((size_t)(t + 1) * NB + rowBase + (i >> 8)) * NYY + (i & 255)];
            __syncthreads();

            // l1 = tanh([h | y] @ Wl1.T + bl1)  (2 cols per lane)
            for (int g = warp; g < 64; g += 16) {
                const int o = g * 8 + c;         // and o+4
                ZA(a0, 8); ZA(a1, 8);
                const float* w0 = Wl1 + (size_t)o * (NXX + NYY);
                const float* w1 = Wl1 + (size_t)(o + 4) * (NXX + NYY);
                dot2<8, 512, 512>(a0, a1, w0, w1, hc, k8);
                dot2<8, 256, 256>(a0, a1, w0 + 512, w1 + 512, ybuf, k8);
                redB<8>(a0); redB<8>(a1);
                l1buf[k8 * 512 + o]     = tanhf(a0[k8] + bl1[o]);
                l1buf[k8 * 512 + o + 4] = tanhf(a1[k8] + bl1[o + 4]);
            }
            __syncthreads();

            // logit = l1 @ Wl2.T + bl2 -> out ; w = tanh(0.5*logit)
            for (int g = warp; g < 64; g += 16) {
                const int o = g * 8 + c;
                ZA(a0, 8); ZA(a1, 8);
                dot2<8, 512, 512>(a0, a1, Wl2 + (size_t)o * 512,
                                  Wl2 + (size_t)(o + 4) * 512, l1buf, k8);
                redB<8>(a0); redB<8>(a1);
                const float lg0 = a0[k8] + bl2[o];
                const float lg1 = a1[k8] + bl2[o + 4];
                float* lrow = out + L_OFF + ((size_t)t * NB + rowBase + k8) * NWW;
                lrow[o]     = lg0;
                lrow[o + 4] = lg1;
                wbuf[k8 * 512 + o]     = tanhf(0.5f * lg0);
                wbuf[k8 * 512 + o + 4] = tanhf(0.5f * lg1);
            }
            __syncthreads();
        } else {
            const unsigned tf = (unsigned)(t - NWUP);
            for (int i = tid; i < 8 * 512; i += 512) {
                const int r = i >> 9, j = i & 511;
                const unsigned idx = ((tf * NB + (unsigned)(rowBase + r)) << 9) + (unsigned)j;
                wbuf[i] = frand_sign(idx);
            }
            __syncthreads();
        }

        // ---- GRU fused: 6 weight rows share each smem read ----
        for (int g = warp; g < 128; g += 16) {
            const int o = g * 4 + c;
            const float* wi = Wih + (size_t)o * 512;
            const float* wh = Whh + (size_t)o * 512;
            ZA(air, 8); ZA(aiz, 8); ZA(ain, 8);
            ZA(ahr, 8); ZA(ahz, 8); ZA(ahn, 8);
            const int kb = 4 * k8;
#pragma unroll 4
            for (int j = 0; j < 16; j++) {
                const int ko = 32 * j + kb;
                float4 vir = *(const float4*)(wi + ko);
                float4 viz = *(const float4*)(wi + 512 * 512 + ko);
                float4 vin = *(const float4*)(wi + 1024 * 512 + ko);
                float4 vhr = *(const float4*)(wh + ko);
                float4 vhz = *(const float4*)(wh + 512 * 512 + ko);
                float4 vhn = *(const float4*)(wh + 1024 * 512 + ko);
#pragma unroll
                for (int r = 0; r < 8; r++) {
                    float4 sw = *(const float4*)(wbuf + r * 512 + ko);
                    float4 sh = *(const float4*)(hc + r * 512 + ko);
                    fma4(air[r], vir, sw);
                    fma4(aiz[r], viz, sw);
                    fma4(ain[r], vin, sw);
                    fma4(ahr[r], vhr, sh);
                    fma4(ahz[r], vhz, sh);
                    fma4(ahn[r], vhn, sh);
                }
            }
            // r,z reduce after linear pre-add; n needs ai/ah separate (r * hn)
#pragma unroll
            for (int r = 0; r < 8; r++) { air[r] += ahr[r]; aiz[r] += ahz[r]; }
            redB<8>(air); redB<8>(aiz); redB<8>(ain); redB<8>(ahn);
            const float rv = sigm(air[k8] + bih[o] + bhh[o]);
            const float zv = sigm(aiz[k8] + bih[o + 512] + bhh[o + 512]);
            const float nv = tanhf(ain[k8] + bih[o + 1024] +
                                   rv * (ahn[k8] + bhh[o + 1024]));
            const float ho = hc[k8 * 512 + o];
            const float hv = (1.0f - zv) * nv + zv * ho;
            hn[k8 * 512 + o] = hv;
            out[((size_t)(t + 1) * NB + rowBase + k8) * NXX + o] = hv;
        }
        __syncthreads();
        float* tmp = hc; hc = hn; hn = tmp;
    }
}

// ---------------------------------------------------------------------------
// Yhat = tanh(X @ Wp1.T + bp1) @ Wp2.T + bp2   (16 rows per CTA, 512 threads)
// ---------------------------------------------------------------------------
__global__ void __launch_bounds__(512) proj_kernel(
    const float* __restrict__ Wp1, const float* __restrict__ bp1,
    const float* __restrict__ Wp2, const float* __restrict__ bp2,
    float* __restrict__ out)
{
    __shared__ float sx[16 * 512];
    __shared__ float st[16 * 512];
    const int tid = threadIdx.x;
    const int warp = tid >> 5, lane = tid & 31;
    const int k8 = lane & 7, c = lane >> 3;
    const size_t rowBase = (size_t)blockIdx.x * 16;

    for (int i = tid; i < 16 * 512; i += 512)
        sx[i] = out[(rowBase + (i >> 9)) * NXX + (i & 511)];
    __syncthreads();

    for (int g = warp; g < 64; g += 16) {
        const int o = g * 8 + c;          // and o+4
        ZA(a0, 16); ZA(a1, 16);
        dot2<16, 512, 512>(a0, a1, Wp1 + (size_t)o * NXX,
                           Wp1 + (size_t)(o + 4) * NXX, sx, k8);
        redB<16>(a0); redB<16>(a1);
        st[k8 * 512 + o]           = tanhf(a0[k8] + bp1[o]);
        st[(k8 + 8) * 512 + o]     = tanhf(a0[k8 + 8] + bp1[o]);
        st[k8 * 512 + o + 4]       = tanhf(a1[k8] + bp1[o + 4]);
        st[(k8 + 8) * 512 + o + 4] = tanhf(a1[k8 + 8] + bp1[o + 4]);
    }
    __syncthreads();

    for (int g = warp; g < 32; g += 16) {
        const int o = g * 8 + c;          // and o+4
        ZA(a0, 16); ZA(a1, 16);
        dot2<16, 512, 512>(a0, a1, Wp2 + (size_t)o * NXX,
                           Wp2 + (size_t)(o + 4) * NXX, st, k8);
        redB<16>(a0); redB<16>(a1);
        float* y0 = out + Y_OFF + (rowBase + k8) * NYY;
        float* y1 = out + Y_OFF + (rowBase + k8 + 8) * NYY;
        y0[o]     = a0[k8]     + bp2[o];
        y1[o]     = a0[k8 + 8] + bp2[o];
        y0[o + 4] = a1[k8]     + bp2[o + 4];
        y1[o + 4] = a1[k8 + 8] + bp2[o + 4];
    }
}

extern "C" void kernel_launch(void* const* d_in, const int* in_sizes, int n_in,
                              void* d_out, int out_size) {
    // dict/signature order: Y0, [Nhrzn,] Wq,bq, Wp1,bp1, Wp2,bp2,
    //                       Wl1,bl1, Wl2,bl2, W_ih,W_hh, b_ih,b_hh
    int off = (n_in >= 16 && in_sizes[1] == 1) ? 2 : 1;
    const float* Y0  = (const float*)d_in[0];
    const float* Wq  = (const float*)d_in[off + 0];
    const float* bq  = (const float*)d_in[off + 1];
    const float* Wp1 = (const float*)d_in[off + 2];
    const float* bp1 = (const float*)d_in[off + 3];
    const float* Wp2 = (const float*)d_in[off + 4];
    const float* bp2 = (const float*)d_in[off + 5];
    const float* Wl1 = (const float*)d_in[off + 6];
    const float* bl1 = (const float*)d_in[off + 7];
    const float* Wl2 = (const float*)d_in[off + 8];
    const float* bl2 = (const float*)d_in[off + 9];
    const float* Wih = (const float*)d_in[off + 10];
    const float* Whh = (const float*)d_in[off + 11];
    const float* bih = (const float*)d_in[off + 12];
    const float* bhh = (const float*)d_in[off + 13];
    float* out = (float*)d_out;

    recur_kernel<<<NB / 8, 512>>>(Y0, Wq, bq, Wl1, bl1, Wl2, bl2,
                                  Wih, Whh, bih, bhh, out);
    proj_kernel<<<(TT * NB) / 16, 512>>>(Wp1, bp1, Wp2, bp2, out);
}

// round 10
// speedup vs baseline: 5.1876x; 2.2230x over previous
#include <cuda_runtime.h>
#include <math.h>

#define NXX   512
#define NWW   512
#define NYY   256
#define NWUP  128
#define NB    1024
#define NHR   32
#define TT    (NWUP + 1 + NHR)          // 161

#define X_SIZE   ((size_t)TT * NB * NXX)
#define L_OFF    (X_SIZE)
#define L_SIZE   ((size_t)NWUP * NB * NWW)
#define Y_OFF    (L_OFF + L_SIZE)

#define ROWS  16                        // batch rows per CTA
#define NCTA  (NB / ROWS)               // 64

// ---- packed tf32 weight buffers (B-fragment order) ----
#define KT_WQ 32
#define KT_L1 96
#define KT_L2 64
#define KT_RZ 128
#define KT_NI 64
#define KT_NH 64
#define OFF_WQ 0
#define SZ_WQ  (64 * KT_WQ * 64)
#define OFF_L1 (OFF_WQ + SZ_WQ)
#define SZ_L1  (64 * KT_L1 * 64)
#define OFF_L2 (OFF_L1 + SZ_L1)
#define SZ_L2  (64 * KT_L2 * 64)
#define OFF_RZ (OFF_L2 + SZ_L2)
#define SZ_RZ  (128 * KT_RZ * 64)
#define OFF_NI (OFF_RZ + SZ_RZ)
#define SZ_NI  (64 * KT_NI * 64)
#define OFF_NH (OFF_NI + SZ_NI)
#define SZ_NH  (64 * KT_NH * 64)
#define WPACK_TOTAL (OFF_NH + SZ_NH)    // 2,359,296 u32 = 9.4 MB

__device__ unsigned g_wpack[WPACK_TOTAL];

// ---- smem layout (unsigned units) ----
#define HYA_OFF 0                        // [16][772]  tf32 [h | y]
#define WHA_OFF 12352                    // [16][1028] tf32 [w | h]
#define L1A_OFF 28800                    // [16][516]  tf32 l1
#define HF_OFF  37056                    // [16][516]  fp32 h
#define SMEM_UNITS 45312                 // 181,248 bytes

__device__ __forceinline__ float sigm(float x) { return 1.0f / (1.0f + expf(-x)); }

__device__ __forceinline__ unsigned f2tf32(float x) {
    unsigned u;
    asm("cvt.rna.tf32.f32 %0, %1;" : "=r"(u) : "f"(x));
    return u;
}

__device__ __forceinline__ void mma8(float c[4], const unsigned a[4],
                                     unsigned b0, unsigned b1) {
    asm("mma.sync.aligned.m16n8k8.row.col.f32.tf32.tf32.f32 "
        "{%0,%1,%2,%3},{%4,%5,%6,%7},{%8,%9},{%0,%1,%2,%3};"
        : "+f"(c[0]), "+f"(c[1]), "+f"(c[2]), "+f"(c[3])
        : "r"(a[0]), "r"(a[1]), "r"(a[2]), "r"(a[3]), "r"(b0), "r"(b1));
}

// JAX partitionable threefry bits: counter (0, i), key (0,1), bits = x0 ^ x1.
__device__ __forceinline__ float frand_sign(unsigned i) {
    const unsigned ks0 = 0u, ks1 = 1u, ks2 = 0x1BD11BDBu;
    unsigned x0 = 0u + ks0;
    unsigned x1 = i  + ks1;
#define QR4(RA,RB,RC,RD) \
    x0 += x1; x1 = __funnelshift_l(x1, x1, RA); x1 ^= x0; \
    x0 += x1; x1 = __funnelshift_l(x1, x1, RB); x1 ^= x0; \
    x0 += x1; x1 = __funnelshift_l(x1, x1, RC); x1 ^= x0; \
    x0 += x1; x1 = __funnelshift_l(x1, x1, RD); x1 ^= x0;
    QR4(13,15,26, 6)  x0 += ks1; x1 += ks2 + 1u;
    QR4(17,29,16,24)  x0 += ks2; x1 += ks0 + 2u;
    QR4(13,15,26, 6)  x0 += ks0; x1 += ks1 + 3u;
    QR4(17,29,16,24)  x0 += ks1; x1 += ks2 + 4u;
    QR4(13,15,26, 6)  x0 += ks2; x1 += ks0 + 5u;
#undef QR4
    return ((x0 ^ x1) & 0x80000000u) ? -1.0f : 1.0f;
}

// ---------------------------------------------------------------------------
// Weight packing: B[k][n] = W[n][k] (with optional K-concat of two sources).
// Fragment layout m16n8k8: b0 = B[t][g], b1 = B[t+4][g]; pair stored contiguous
// so each lane loads both regs with one LDG.64.
// ---------------------------------------------------------------------------
__device__ void packSeg(unsigned* dst, const float* S1, int ld1,
                        const float* S2, int ld2, int ksplit,
                        int N, int KTl, int tid, int nth) {
    const int tot = (N / 8) * KTl * 32;
    for (int p = tid; p < tot; p += nth) {
        const int lane = p & 31, kt = (p >> 5) % KTl, nt = (p >> 5) / KTl;
        const int g = lane >> 2, t = lane & 3;
        const int n = nt * 8 + g;
        const int k0 = kt * 8 + t, k1 = k0 + 4;
        float v0 = (k0 < ksplit) ? S1[(size_t)n * ld1 + k0] : S2[(size_t)n * ld2 + (k0 - ksplit)];
        float v1 = (k1 < ksplit) ? S1[(size_t)n * ld1 + k1] : S2[(size_t)n * ld2 + (k1 - ksplit)];
        dst[(size_t)p * 2]     = f2tf32(v0);
        dst[(size_t)p * 2 + 1] = f2tf32(v1);
    }
}

__global__ void pack_kernel(const float* __restrict__ Wq,  const float* __restrict__ Wl1,
                            const float* __restrict__ Wl2, const float* __restrict__ Wih,
                            const float* __restrict__ Whh) {
    const int tid = blockIdx.x * blockDim.x + threadIdx.x;
    const int nth = gridDim.x * blockDim.x;
    packSeg(g_wpack + OFF_WQ, Wq, 256, Wq, 256, 256, 512, KT_WQ, tid, nth);
    packSeg(g_wpack + OFF_L1, Wl1, 768, Wl1, 768, 768, 512, KT_L1, tid, nth);
    packSeg(g_wpack + OFF_L2, Wl2, 512, Wl2, 512, 512, 512, KT_L2, tid, nth);
    packSeg(g_wpack + OFF_RZ, Wih, 512, Whh, 512, 512, 1024, KT_RZ, tid, nth);  // [w|h] K-fused
    packSeg(g_wpack + OFF_NI, Wih + 1024 * 512, 512, Wih, 512, 512, 512, KT_NI, tid, nth);
    packSeg(g_wpack + OFF_NH, Whh + 1024 * 512, 512, Whh, 512, 512, 512, KT_NH, tid, nth);
}

// A-fragment load (m16n8k8 tf32): a0=(g,t) a1=(g+8,t) a2=(g,t+4) a3=(g+8,t+4)
template<int STRIDE>
__device__ __forceinline__ void ldA(unsigned a[4], const unsigned* As, int kt, int g, int t) {
    const unsigned* p = As + g * STRIDE + kt * 8 + t;
    a[0] = p[0];
    a[1] = p[8 * STRIDE];
    a[2] = p[4];
    a[3] = p[8 * STRIDE + 4];
}

template<int NT, int KTL, int STRIDE>
__device__ __forceinline__ void gemmW(float C[NT][4], const unsigned* __restrict__ Bp,
                                      const unsigned* As, const int* tiles, int lane,
                                      int g, int t) {
    const unsigned* bptr[NT];
#pragma unroll
    for (int i = 0; i < NT; i++)
        bptr[i] = Bp + (size_t)tiles[i] * KTL * 64 + lane * 2;
#pragma unroll 4
    for (int kt = 0; kt < KTL; kt++) {
        unsigned a[4];
        ldA<STRIDE>(a, As, kt, g, t);
#pragma unroll
        for (int i = 0; i < NT; i++) {
            uint2 b = *(const uint2*)(bptr[i] + kt * 64);
            mma8(C[i], a, b.x, b.y);
        }
    }
}

#define ZC(C, n) float C[n][4]; _Pragma("unroll") for (int _i = 0; _i < n; _i++) { \
    C[_i][0] = 0.f; C[_i][1] = 0.f; C[_i][2] = 0.f; C[_i][3] = 0.f; }

// ---------------------------------------------------------------------------
// Persistent recurrence. 64 CTAs x 512 threads (16 warps), 16 rows/CTA.
// ---------------------------------------------------------------------------
__global__ void __launch_bounds__(512, 1) recur_kernel(
    const float* __restrict__ Y0,
    const float* __restrict__ bq,
    const float* __restrict__ bl1, const float* __restrict__ bl2,
    const float* __restrict__ bih, const float* __restrict__ bhh,
    float* __restrict__ out)
{
    extern __shared__ unsigned smemU[];
    float* hF = (float*)(smemU + HF_OFF);

    const int tid  = threadIdx.x;
    const int warp = tid >> 5, lane = tid & 31;
    const int g = lane >> 2, t = lane & 3;
    const int rowBase = blockIdx.x * ROWS;
    int tiles4[4], tiles8[8];
#pragma unroll
    for (int i = 0; i < 4; i++) { tiles4[i] = 4 * warp + i; tiles8[i] = 4 * warp + i; }
#pragma unroll
    for (int i = 0; i < 4; i++) tiles8[4 + i] = 64 + 4 * warp + i;

    // h-write helper (fp32 h + tf32 mirrors + gmem X)
    auto put_h = [&](int tstep, int row, int col, float v) {
        hF[row * 516 + col] = v;
        unsigned u = f2tf32(v);
        smemU[HYA_OFF + row * 772 + col] = u;
        smemU[WHA_OFF + row * 1028 + 512 + col] = u;
        out[((size_t)tstep * NB + rowBase + row) * NXX + col] = v;
    };

    // ---- x0 = tanh(Y0[0] @ Wq.T + bq) ----
    for (int i = tid; i < 16 * 256; i += 512) {
        const int r = i >> 8, cl = i & 255;
        smemU[HYA_OFF + r * 772 + 512 + cl] = f2tf32(Y0[(size_t)(rowBase + r) * NYY + cl]);
    }
    __syncthreads();
    {
        ZC(C, 4);
        gemmW<4, KT_WQ, 772>(C, g_wpack + OFF_WQ, smemU + HYA_OFF + 512, tiles4, lane, g, t);
        __syncthreads();   // all reads of y done before h-region writes (none overlap, but keep order clean)
#pragma unroll
        for (int i = 0; i < 4; i++) {
            const int j0 = 32 * warp + i * 8 + 2 * t;
            put_h(0, g,     j0,     tanhf(C[i][0] + bq[j0]));
            put_h(0, g,     j0 + 1, tanhf(C[i][1] + bq[j0 + 1]));
            put_h(0, g + 8, j0,     tanhf(C[i][2] + bq[j0]));
            put_h(0, g + 8, j0 + 1, tanhf(C[i][3] + bq[j0 + 1]));
        }
    }
    __syncthreads();

    // ---- 160 sequential steps ----
    for (int tstep = 0; tstep < NWUP + NHR; tstep++) {
        if (tstep < NWUP) {
            // y = Y0[t+1] -> hyA y-region
            for (int i = tid; i < 16 * 256; i += 512) {
                const int r = i >> 8, cl = i & 255;
                smemU[HYA_OFF + r * 772 + 512 + cl] =
                    f2tf32(Y0[((size_t)(tstep + 1) * NB + rowBase + r) * NYY + cl]);
            }
            __syncthreads();

            // l1 = tanh([h|y] @ Wl1.T + bl1) -> l1A (tf32)
            {
                ZC(C, 4);
                gemmW<4, KT_L1, 772>(C, g_wpack + OFF_L1, smemU + HYA_OFF, tiles4, lane, g, t);
#pragma unroll
                for (int i = 0; i < 4; i++) {
                    const int j0 = 32 * warp + i * 8 + 2 * t;
                    smemU[L1A_OFF + g * 516 + j0]           = f2tf32(tanhf(C[i][0] + bl1[j0]));
                    smemU[L1A_OFF + g * 516 + j0 + 1]       = f2tf32(tanhf(C[i][1] + bl1[j0 + 1]));
                    smemU[L1A_OFF + (g + 8) * 516 + j0]     = f2tf32(tanhf(C[i][2] + bl1[j0]));
                    smemU[L1A_OFF + (g + 8) * 516 + j0 + 1] = f2tf32(tanhf(C[i][3] + bl1[j0 + 1]));
                }
            }
            __syncthreads();

            // logit = l1 @ Wl2.T + bl2 -> out ; w = tanh(0.5*logit) -> whA w-region
            {
                ZC(C, 4);
                gemmW<4, KT_L2, 516>(C, g_wpack + OFF_L2, smemU + L1A_OFF, tiles4, lane, g, t);
                float* lbase = out + L_OFF + ((size_t)tstep * NB + rowBase) * NWW;
#pragma unroll
                for (int i = 0; i < 4; i++) {
                    const int j0 = 32 * warp + i * 8 + 2 * t;
#pragma unroll
                    for (int cc = 0; cc < 2; cc++) {
                        const int j = j0 + cc;
                        const float lg0 = C[i][cc]     + bl2[j];   // row g
                        const float lg1 = C[i][2 + cc] + bl2[j];   // row g+8
                        lbase[(size_t)g * NWW + j]       = lg0;
                        lbase[(size_t)(g + 8) * NWW + j] = lg1;
                        smemU[WHA_OFF + g * 1028 + j]       = f2tf32(tanhf(0.5f * lg0));
                        smemU[WHA_OFF + (g + 8) * 1028 + j] = f2tf32(tanhf(0.5f * lg1));
                    }
                }
            }
            __syncthreads();
        } else {
            // free-run: w = +/-1 (exact in tf32)
            const unsigned tf = (unsigned)(tstep - NWUP);
            for (int i = tid; i < 16 * 512; i += 512) {
                const int r = i >> 9, j = i & 511;
                const unsigned idx = ((tf * NB + (unsigned)(rowBase + r)) << 9) + (unsigned)j;
                smemU[WHA_OFF + r * 1028 + j] = __float_as_uint(frand_sign(idx));
            }
            __syncthreads();
        }

        // ---- GRU: rz (K=1024 fused), n-input (K=512, w), n-hidden (K=512, h) ----
        ZC(Crz, 8);
        gemmW<8, KT_RZ, 1028>(Crz, g_wpack + OFF_RZ, smemU + WHA_OFF, tiles8, lane, g, t);
        ZC(Cni, 4);
        gemmW<4, KT_NI, 1028>(Cni, g_wpack + OFF_NI, smemU + WHA_OFF, tiles4, lane, g, t);
        ZC(Cnh, 4);
        gemmW<4, KT_NH, 1028>(Cnh, g_wpack + OFF_NH, smemU + WHA_OFF + 512, tiles4, lane, g, t);
        __syncthreads();   // all warps done reading whA/h before h updates

#pragma unroll
        for (int i = 0; i < 4; i++) {
            const int j0 = 32 * warp + i * 8 + 2 * t;
#pragma unroll
            for (int cc = 0; cc < 2; cc++) {
                const int j = j0 + cc;
                const float br  = bih[j] + bhh[j];
                const float bz  = bih[j + 512] + bhh[j + 512];
                const float bi3 = bih[j + 1024], bh3 = bhh[j + 1024];
                // row g
                {
                    const float r = sigm(Crz[i][cc] + br);
                    const float z = sigm(Crz[4 + i][cc] + bz);
                    const float n = tanhf(Cni[i][cc] + bi3 + r * (Cnh[i][cc] + bh3));
                    const float ho = hF[g * 516 + j];
                    put_h(tstep + 1, g, j, (1.0f - z) * n + z * ho);
                }
                // row g+8
                {
                    const float r = sigm(Crz[i][2 + cc] + br);
                    const float z = sigm(Crz[4 + i][2 + cc] + bz);
                    const float n = tanhf(Cni[i][2 + cc] + bi3 + r * (Cnh[i][2 + cc] + bh3));
                    const float ho = hF[(g + 8) * 516 + j];
                    put_h(tstep + 1, g + 8, j, (1.0f - z) * n + z * ho);
                }
            }
        }
        __syncthreads();
    }
}

// ---------------------------------------------------------------------------
// proj (unchanged from passing R9): Yhat = tanh(X @ Wp1.T + bp1) @ Wp2.T + bp2
// ---------------------------------------------------------------------------
__device__ __forceinline__ void fma4(float& a, const float4& u, const float4& v) {
    a = fmaf(u.x, v.x, a); a = fmaf(u.y, v.y, a);
    a = fmaf(u.z, v.z, a); a = fmaf(u.w, v.w, a);
}
template<int NR, int KLEN, int STRIDE>
__device__ __forceinline__ void dot2(float* a0, float* a1,
                                     const float* __restrict__ W0,
                                     const float* __restrict__ W1,
                                     const float* __restrict__ S, int k8) {
    const int kb = 4 * k8;
#pragma unroll 4
    for (int j = 0; j < KLEN / 32; j++) {
        const int ko = 32 * j + kb;
        float4 w0 = *(const float4*)(W0 + ko);
        float4 w1 = *(const float4*)(W1 + ko);
#pragma unroll
        for (int r = 0; r < NR; r++) {
            float4 sv = *(const float4*)(S + r * STRIDE + ko);
            fma4(a0[r], w0, sv);
            fma4(a1[r], w1, sv);
        }
    }
}
template<int NR>
__device__ __forceinline__ void redB(float* acc) {
#pragma unroll
    for (int r = 0; r < NR; r++) {
        acc[r] += __shfl_xor_sync(0xffffffffu, acc[r], 1);
        acc[r] += __shfl_xor_sync(0xffffffffu, acc[r], 2);
        acc[r] += __shfl_xor_sync(0xffffffffu, acc[r], 4);
    }
}
#define ZAP(a, n) float a[n]; _Pragma("unroll") for (int _z = 0; _z < n; _z++) a[_z] = 0.0f;

__global__ void __launch_bounds__(512) proj_kernel(
    const float* __restrict__ Wp1, const float* __restrict__ bp1,
    const float* __restrict__ Wp2, const float* __restrict__ bp2,
    float* __restrict__ out)
{
    __shared__ float sx[16 * 512];
    __shared__ float st[16 * 512];
    const int tid = threadIdx.x;
    const int warp = tid >> 5, lane = tid & 31;
    const int k8 = lane & 7, c = lane >> 3;
    const size_t rowBase = (size_t)blockIdx.x * 16;

    for (int i = tid; i < 16 * 512; i += 512)
        sx[i] = out[(rowBase + (i >> 9)) * NXX + (i & 511)];
    __syncthreads();

    for (int g = warp; g < 64; g += 16) {
        const int o = g * 8 + c;
        ZAP(a0, 16); ZAP(a1, 16);
        dot2<16, 512, 512>(a0, a1, Wp1 + (size_t)o * NXX,
                           Wp1 + (size_t)(o + 4) * NXX, sx, k8);
        redB<16>(a0); redB<16>(a1);
        st[k8 * 512 + o]           = tanhf(a0[k8] + bp1[o]);
        st[(k8 + 8) * 512 + o]     = tanhf(a0[k8 + 8] + bp1[o]);
        st[k8 * 512 + o + 4]       = tanhf(a1[k8] + bp1[o + 4]);
        st[(k8 + 8) * 512 + o + 4] = tanhf(a1[k8 + 8] + bp1[o + 4]);
    }
    __syncthreads();

    for (int g = warp; g < 32; g += 16) {
        const int o = g * 8 + c;
        ZAP(a0, 16); ZAP(a1, 16);
        dot2<16, 512, 512>(a0, a1, Wp2 + (size_t)o * NXX,
                           Wp2 + (size_t)(o + 4) * NXX, st, k8);
        redB<16>(a0); redB<16>(a1);
        float* y0 = out + Y_OFF + (rowBase + k8) * NYY;
        float* y1 = out + Y_OFF + (rowBase + k8 + 8) * NYY;
        y0[o]     = a0[k8]     + bp2[o];
        y1[o]     = a0[k8 + 8] + bp2[o];
        y0[o + 4] = a1[k8]     + bp2[o + 4];
        y1[o + 4] = a1[k8 + 8] + bp2[o + 4];
    }
}

extern "C" void kernel_launch(void* const* d_in, const int* in_sizes, int n_in,
                              void* d_out, int out_size) {
    // dict/signature order: Y0, [Nhrzn,] Wq,bq, Wp1,bp1, Wp2,bp2,
    //                       Wl1,bl1, Wl2,bl2, W_ih,W_hh, b_ih,b_hh
    int off = (n_in >= 16 && in_sizes[1] == 1) ? 2 : 1;
    const float* Y0  = (const float*)d_in[0];
    const float* Wq  = (const float*)d_in[off + 0];
    const float* bq  = (const float*)d_in[off + 1];
    const float* Wp1 = (const float*)d_in[off + 2];
    const float* bp1 = (const float*)d_in[off + 3];
    const float* Wp2 = (const float*)d_in[off + 4];
    const float* bp2 = (const float*)d_in[off + 5];
    const float* Wl1 = (const float*)d_in[off + 6];
    const float* bl1 = (const float*)d_in[off + 7];
    const float* Wl2 = (const float*)d_in[off + 8];
    const float* bl2 = (const float*)d_in[off + 9];
    const float* Wih = (const float*)d_in[off + 10];
    const float* Whh = (const float*)d_in[off + 11];
    const float* bih = (const float*)d_in[off + 12];
    const float* bhh = (const float*)d_in[off + 13];
    float* out = (float*)d_out;

    static int smem_set = 0;
    if (!smem_set) {
        cudaFuncSetAttribute(recur_kernel, cudaFuncAttributeMaxDynamicSharedMemorySize,
                             SMEM_UNITS * 4);
        smem_set = 1;
    }

    pack_kernel<<<128, 256>>>(Wq, Wl1, Wl2, Wih, Whh);
    recur_kernel<<<NCTA, 512, SMEM_UNITS * 4>>>(Y0, bq, bl1, bl2, bih, bhh, out);
    proj_kernel<<<(TT * NB) / 16, 512>>>(Wp1, bp1, Wp2, bp2, out);
}

// round 11
// speedup vs baseline: 7.6179x; 1.4685x over previous
#include <cuda_runtime.h>
#include <math.h>

#define NXX   512
#define NWW   512
#define NYY   256
#define NWUP  128
#define NB    1024
#define NHR   32
#define TT    (NWUP + 1 + NHR)          // 161

#define X_SIZE   ((size_t)TT * NB * NXX)
#define L_OFF    (X_SIZE)
#define L_SIZE   ((size_t)NWUP * NB * NWW)
#define Y_OFF    (L_OFF + L_SIZE)

#define ROWS  16                        // batch rows per CTA (recurrence)
#define NCTA  (NB / ROWS)               // 64

// ---- packed tf32 weight buffers (B-fragment order) ----
#define KT_WQ 32
#define KT_L1 96
#define KT_L2 64
#define KT_RZ 128
#define KT_NI 64
#define KT_NH 64
#define KT_P1 64
#define KT_P2 64
#define OFF_WQ 0
#define SZ_WQ  (64 * KT_WQ * 64)
#define OFF_L1 (OFF_WQ + SZ_WQ)
#define SZ_L1  (64 * KT_L1 * 64)
#define OFF_L2 (OFF_L1 + SZ_L1)
#define SZ_L2  (64 * KT_L2 * 64)
#define OFF_RZ (OFF_L2 + SZ_L2)
#define SZ_RZ  (128 * KT_RZ * 64)
#define OFF_NI (OFF_RZ + SZ_RZ)
#define SZ_NI  (64 * KT_NI * 64)
#define OFF_NH (OFF_NI + SZ_NI)
#define SZ_NH  (64 * KT_NH * 64)
#define OFF_P1 (OFF_NH + SZ_NH)
#define SZ_P1  (64 * KT_P1 * 64)
#define OFF_P2 (OFF_P1 + SZ_P1)
#define SZ_P2  (32 * KT_P2 * 64)
#define WPACK_TOTAL (OFF_P2 + SZ_P2)

__device__ unsigned g_wpack[WPACK_TOTAL];

// ---- recurrence smem layout (unsigned units) ----
#define HYA_OFF 0                        // [16][772]  tf32 [h | y]
#define WHA_OFF 12352                    // [16][1028] tf32 [w | h]
#define L1A_OFF 28800                    // [16][516]  tf32 l1
#define HF_OFF  37056                    // [16][516]  fp32 h
#define SMEM_UNITS 45312                 // 181,248 bytes

// ---- proj smem: [64][516] tf32 ----
#define PROJ_ROWS 64
#define PROJ_SMEM_UNITS (PROJ_ROWS * 516)   // 33,024 u32 = 132,096 B

__device__ __forceinline__ float sigm(float x) { return 1.0f / (1.0f + expf(-x)); }

__device__ __forceinline__ unsigned f2tf32(float x) {
    unsigned u;
    asm("cvt.rna.tf32.f32 %0, %1;" : "=r"(u) : "f"(x));
    return u;
}

__device__ __forceinline__ void mma8(float c[4], const unsigned a[4],
                                     unsigned b0, unsigned b1) {
    asm("mma.sync.aligned.m16n8k8.row.col.f32.tf32.tf32.f32 "
        "{%0,%1,%2,%3},{%4,%5,%6,%7},{%8,%9},{%0,%1,%2,%3};"
        : "+f"(c[0]), "+f"(c[1]), "+f"(c[2]), "+f"(c[3])
        : "r"(a[0]), "r"(a[1]), "r"(a[2]), "r"(a[3]), "r"(b0), "r"(b1));
}

// JAX partitionable threefry bits: counter (0, i), key (0,1), bits = x0 ^ x1.
__device__ __forceinline__ float frand_sign(unsigned i) {
    const unsigned ks0 = 0u, ks1 = 1u, ks2 = 0x1BD11BDBu;
    unsigned x0 = 0u + ks0;
    unsigned x1 = i  + ks1;
#define QR4(RA,RB,RC,RD) \
    x0 += x1; x1 = __funnelshift_l(x1, x1, RA); x1 ^= x0; \
    x0 += x1; x1 = __funnelshift_l(x1, x1, RB); x1 ^= x0; \
    x0 += x1; x1 = __funnelshift_l(x1, x1, RC); x1 ^= x0; \
    x0 += x1; x1 = __funnelshift_l(x1, x1, RD); x1 ^= x0;
    QR4(13,15,26, 6)  x0 += ks1; x1 += ks2 + 1u;
    QR4(17,29,16,24)  x0 += ks2; x1 += ks0 + 2u;
    QR4(13,15,26, 6)  x0 += ks0; x1 += ks1 + 3u;
    QR4(17,29,16,24)  x0 += ks1; x1 += ks2 + 4u;
    QR4(13,15,26, 6)  x0 += ks2; x1 += ks0 + 5u;
#undef QR4
    return ((x0 ^ x1) & 0x80000000u) ? -1.0f : 1.0f;
}

// ---------------------------------------------------------------------------
// Weight packing: B[k][n] = W[n][k] (optional K-concat). m16n8k8 fragment:
// b0 = B[t][g], b1 = B[t+4][g]; pair contiguous -> one LDG.64 per lane.
// ---------------------------------------------------------------------------
__device__ void packSeg(unsigned* dst, const float* S1, int ld1,
                        const float* S2, int ld2, int ksplit,
                        int N, int KTl, int tid, int nth) {
    const int tot = (N / 8) * KTl * 32;
    for (int p = tid; p < tot; p += nth) {
        const int lane = p & 31, kt = (p >> 5) % KTl, nt = (p >> 5) / KTl;
        const int g = lane >> 2, t = lane & 3;
        const int n = nt * 8 + g;
        const int k0 = kt * 8 + t, k1 = k0 + 4;
        float v0 = (k0 < ksplit) ? S1[(size_t)n * ld1 + k0] : S2[(size_t)n * ld2 + (k0 - ksplit)];
        float v1 = (k1 < ksplit) ? S1[(size_t)n * ld1 + k1] : S2[(size_t)n * ld2 + (k1 - ksplit)];
        dst[(size_t)p * 2]     = f2tf32(v0);
        dst[(size_t)p * 2 + 1] = f2tf32(v1);
    }
}

__global__ void pack_kernel(const float* __restrict__ Wq,  const float* __restrict__ Wl1,
                            const float* __restrict__ Wl2, const float* __restrict__ Wih,
                            const float* __restrict__ Whh, const float* __restrict__ Wp1,
                            const float* __restrict__ Wp2) {
    const int tid = blockIdx.x * blockDim.x + threadIdx.x;
    const int nth = gridDim.x * blockDim.x;
    packSeg(g_wpack + OFF_WQ, Wq, 256, Wq, 256, 256, 512, KT_WQ, tid, nth);
    packSeg(g_wpack + OFF_L1, Wl1, 768, Wl1, 768, 768, 512, KT_L1, tid, nth);
    packSeg(g_wpack + OFF_L2, Wl2, 512, Wl2, 512, 512, 512, KT_L2, tid, nth);
    packSeg(g_wpack + OFF_RZ, Wih, 512, Whh, 512, 512, 1024, KT_RZ, tid, nth);  // [w|h] K-fused
    packSeg(g_wpack + OFF_NI, Wih + 1024 * 512, 512, Wih, 512, 512, 512, KT_NI, tid, nth);
    packSeg(g_wpack + OFF_NH, Whh + 1024 * 512, 512, Whh, 512, 512, 512, KT_NH, tid, nth);
    packSeg(g_wpack + OFF_P1, Wp1, 512, Wp1, 512, 512, 512, KT_P1, tid, nth);
    packSeg(g_wpack + OFF_P2, Wp2, 512, Wp2, 512, 512, 256, KT_P2, tid, nth);
}

// A-fragment load (m16n8k8 tf32): a0=(g,t) a1=(g+8,t) a2=(g,t+4) a3=(g+8,t+4)
template<int STRIDE>
__device__ __forceinline__ void ldA(unsigned a[4], const unsigned* As, int kt, int g, int t) {
    const unsigned* p = As + g * STRIDE + kt * 8 + t;
    a[0] = p[0];
    a[1] = p[8 * STRIDE];
    a[2] = p[4];
    a[3] = p[8 * STRIDE + 4];
}

template<int NT, int KTL, int STRIDE>
__device__ __forceinline__ void gemmW(float C[NT][4], const unsigned* __restrict__ Bp,
                                      const unsigned* As, const int* tiles, int lane,
                                      int g, int t) {
    const unsigned* bptr[NT];
#pragma unroll
    for (int i = 0; i < NT; i++)
        bptr[i] = Bp + (size_t)tiles[i] * KTL * 64 + lane * 2;
#pragma unroll 4
    for (int kt = 0; kt < KTL; kt++) {
        unsigned a[4];
        ldA<STRIDE>(a, As, kt, g, t);
#pragma unroll
        for (int i = 0; i < NT; i++) {
            uint2 b = *(const uint2*)(bptr[i] + kt * 64);
            mma8(C[i], a, b.x, b.y);
        }
    }
}

#define ZC(C, n) float C[n][4]; _Pragma("unroll") for (int _i = 0; _i < n; _i++) { \
    C[_i][0] = 0.f; C[_i][1] = 0.f; C[_i][2] = 0.f; C[_i][3] = 0.f; }

// ---------------------------------------------------------------------------
// Persistent recurrence (UNCHANGED from passing R10). 64 CTAs x 512 threads.
// ---------------------------------------------------------------------------
__global__ void __launch_bounds__(512, 1) recur_kernel(
    const float* __restrict__ Y0,
    const float* __restrict__ bq,
    const float* __restrict__ bl1, const float* __restrict__ bl2,
    const float* __restrict__ bih, const float* __restrict__ bhh,
    float* __restrict__ out)
{
    extern __shared__ unsigned smemU[];
    float* hF = (float*)(smemU + HF_OFF);

    const int tid  = threadIdx.x;
    const int warp = tid >> 5, lane = tid & 31;
    const int g = lane >> 2, t = lane & 3;
    const int rowBase = blockIdx.x * ROWS;
    int tiles4[4], tiles8[8];
#pragma unroll
    for (int i = 0; i < 4; i++) { tiles4[i] = 4 * warp + i; tiles8[i] = 4 * warp + i; }
#pragma unroll
    for (int i = 0; i < 4; i++) tiles8[4 + i] = 64 + 4 * warp + i;

    auto put_h = [&](int tstep, int row, int col, float v) {
        hF[row * 516 + col] = v;
        unsigned u = f2tf32(v);
        smemU[HYA_OFF + row * 772 + col] = u;
        smemU[WHA_OFF + row * 1028 + 512 + col] = u;
        out[((size_t)tstep * NB + rowBase + row) * NXX + col] = v;
    };

    // ---- x0 = tanh(Y0[0] @ Wq.T + bq) ----
    for (int i = tid; i < 16 * 256; i += 512) {
        const int r = i >> 8, cl = i & 255;
        smemU[HYA_OFF + r * 772 + 512 + cl] = f2tf32(Y0[(size_t)(rowBase + r) * NYY + cl]);
    }
    __syncthreads();
    {
        ZC(C, 4);
        gemmW<4, KT_WQ, 772>(C, g_wpack + OFF_WQ, smemU + HYA_OFF + 512, tiles4, lane, g, t);
        __syncthreads();
#pragma unroll
        for (int i = 0; i < 4; i++) {
            const int j0 = 32 * warp + i * 8 + 2 * t;
            put_h(0, g,     j0,     tanhf(C[i][0] + bq[j0]));
            put_h(0, g,     j0 + 1, tanhf(C[i][1] + bq[j0 + 1]));
            put_h(0, g + 8, j0,     tanhf(C[i][2] + bq[j0]));
            put_h(0, g + 8, j0 + 1, tanhf(C[i][3] + bq[j0 + 1]));
        }
    }
    __syncthreads();

    // ---- 160 sequential steps ----
    for (int tstep = 0; tstep < NWUP + NHR; tstep++) {
        if (tstep < NWUP) {
            for (int i = tid; i < 16 * 256; i += 512) {
                const int r = i >> 8, cl = i & 255;
                smemU[HYA_OFF + r * 772 + 512 + cl] =
                    f2tf32(Y0[((size_t)(tstep + 1) * NB + rowBase + r) * NYY + cl]);
            }
            __syncthreads();

            {
                ZC(C, 4);
                gemmW<4, KT_L1, 772>(C, g_wpack + OFF_L1, smemU + HYA_OFF, tiles4, lane, g, t);
#pragma unroll
                for (int i = 0; i < 4; i++) {
                    const int j0 = 32 * warp + i * 8 + 2 * t;
                    smemU[L1A_OFF + g * 516 + j0]           = f2tf32(tanhf(C[i][0] + bl1[j0]));
                    smemU[L1A_OFF + g * 516 + j0 + 1]       = f2tf32(tanhf(C[i][1] + bl1[j0 + 1]));
                    smemU[L1A_OFF + (g + 8) * 516 + j0]     = f2tf32(tanhf(C[i][2] + bl1[j0]));
                    smemU[L1A_OFF + (g + 8) * 516 + j0 + 1] = f2tf32(tanhf(C[i][3] + bl1[j0 + 1]));
                }
            }
            __syncthreads();

            {
                ZC(C, 4);
                gemmW<4, KT_L2, 516>(C, g_wpack + OFF_L2, smemU + L1A_OFF, tiles4, lane, g, t);
                float* lbase = out + L_OFF + ((size_t)tstep * NB + rowBase) * NWW;
#pragma unroll
                for (int i = 0; i < 4; i++) {
                    const int j0 = 32 * warp + i * 8 + 2 * t;
#pragma unroll
                    for (int cc = 0; cc < 2; cc++) {
                        const int j = j0 + cc;
                        const float lg0 = C[i][cc]     + bl2[j];
                        const float lg1 = C[i][2 + cc] + bl2[j];
                        lbase[(size_t)g * NWW + j]       = lg0;
                        lbase[(size_t)(g + 8) * NWW + j] = lg1;
                        smemU[WHA_OFF + g * 1028 + j]       = f2tf32(tanhf(0.5f * lg0));
                        smemU[WHA_OFF + (g + 8) * 1028 + j] = f2tf32(tanhf(0.5f * lg1));
                    }
                }
            }
            __syncthreads();
        } else {
            const unsigned tf = (unsigned)(tstep - NWUP);
            for (int i = tid; i < 16 * 512; i += 512) {
                const int r = i >> 9, j = i & 511;
                const unsigned idx = ((tf * NB + (unsigned)(rowBase + r)) << 9) + (unsigned)j;
                smemU[WHA_OFF + r * 1028 + j] = __float_as_uint(frand_sign(idx));
            }
            __syncthreads();
        }

        ZC(Crz, 8);
        gemmW<8, KT_RZ, 1028>(Crz, g_wpack + OFF_RZ, smemU + WHA_OFF, tiles8, lane, g, t);
        ZC(Cni, 4);
        gemmW<4, KT_NI, 1028>(Cni, g_wpack + OFF_NI, smemU + WHA_OFF, tiles4, lane, g, t);
        ZC(Cnh, 4);
        gemmW<4, KT_NH, 1028>(Cnh, g_wpack + OFF_NH, smemU + WHA_OFF + 512, tiles4, lane, g, t);
        __syncthreads();

#pragma unroll
        for (int i = 0; i < 4; i++) {
            const int j0 = 32 * warp + i * 8 + 2 * t;
#pragma unroll
            for (int cc = 0; cc < 2; cc++) {
                const int j = j0 + cc;
                const float br  = bih[j] + bhh[j];
                const float bz  = bih[j + 512] + bhh[j + 512];
                const float bi3 = bih[j + 1024], bh3 = bhh[j + 1024];
                {
                    const float r = sigm(Crz[i][cc] + br);
                    const float z = sigm(Crz[4 + i][cc] + bz);
                    const float n = tanhf(Cni[i][cc] + bi3 + r * (Cnh[i][cc] + bh3));
                    const float ho = hF[g * 516 + j];
                    put_h(tstep + 1, g, j, (1.0f - z) * n + z * ho);
                }
                {
                    const float r = sigm(Crz[i][2 + cc] + br);
                    const float z = sigm(Crz[4 + i][2 + cc] + bz);
                    const float n = tanhf(Cni[i][2 + cc] + bi3 + r * (Cnh[i][2 + cc] + bh3));
                    const float ho = hF[(g + 8) * 516 + j];
                    put_h(tstep + 1, g + 8, j, (1.0f - z) * n + z * ho);
                }
            }
        }
        __syncthreads();
    }
}

// ---------------------------------------------------------------------------
// proj (NEW, tf32 mma): Yhat = tanh(X @ Wp1.T + bp1) @ Wp2.T + bp2
// 64 rows/CTA, 512 threads. XA smem reused for layer-1 output (reg-carried).
// ---------------------------------------------------------------------------
__global__ void __launch_bounds__(512, 1) proj_kernel(
    const float* __restrict__ bp1, const float* __restrict__ bp2,
    float* __restrict__ out)
{
    extern __shared__ unsigned XA[];     // [64][516] tf32
    const int tid = threadIdx.x, warp = tid >> 5, lane = tid & 31;
    const int g = lane >> 2, t = lane & 3;
    const size_t rowBase = (size_t)blockIdx.x * PROJ_ROWS;

    for (int i = tid; i < PROJ_ROWS * 512; i += 512) {
        const int r = i >> 9, cl = i & 511;
        XA[r * 516 + cl] = f2tf32(out[(rowBase + r) * NXX + cl]);
    }
    __syncthreads();

    // GEMM1: N=512 (warp n-tiles 4w..4w+3), M=64 (4 m-tiles)
    float C[4][4][4];
#pragma unroll
    for (int m = 0; m < 4; m++)
#pragma unroll
        for (int i = 0; i < 4; i++) { C[m][i][0]=0.f; C[m][i][1]=0.f; C[m][i][2]=0.f; C[m][i][3]=0.f; }
    {
        const unsigned* bbase = g_wpack + OFF_P1 + (size_t)(4 * warp) * KT_P1 * 64 + lane * 2;
#pragma unroll 2
        for (int kt = 0; kt < KT_P1; kt++) {
            unsigned a[4][4];
#pragma unroll
            for (int m = 0; m < 4; m++) ldA<516>(a[m], XA + m * 16 * 516, kt, g, t);
#pragma unroll
            for (int i = 0; i < 4; i++) {
                uint2 b = *(const uint2*)(bbase + (size_t)i * KT_P1 * 64 + kt * 64);
#pragma unroll
                for (int m = 0; m < 4; m++) mma8(C[m][i], a[m], b.x, b.y);
            }
        }
    }
    __syncthreads();   // all XA reads done before aliased write
#pragma unroll
    for (int m = 0; m < 4; m++)
#pragma unroll
        for (int i = 0; i < 4; i++) {
            const int j0 = 32 * warp + i * 8 + 2 * t;
            XA[(m * 16 + g) * 516 + j0]         = f2tf32(tanhf(C[m][i][0] + bp1[j0]));
            XA[(m * 16 + g) * 516 + j0 + 1]     = f2tf32(tanhf(C[m][i][1] + bp1[j0 + 1]));
            XA[(m * 16 + g + 8) * 516 + j0]     = f2tf32(tanhf(C[m][i][2] + bp1[j0]));
            XA[(m * 16 + g + 8) * 516 + j0 + 1] = f2tf32(tanhf(C[m][i][3] + bp1[j0 + 1]));
        }
    __syncthreads();

    // GEMM2: N=256 (warp n-tiles 2w, 2w+1), M=64
    float C2[4][2][4];
#pragma unroll
    for (int m = 0; m < 4; m++)
#pragma unroll
        for (int i = 0; i < 2; i++) { C2[m][i][0]=0.f; C2[m][i][1]=0.f; C2[m][i][2]=0.f; C2[m][i][3]=0.f; }
    {
        const unsigned* bbase = g_wpack + OFF_P2 + (size_t)(2 * warp) * KT_P2 * 64 + lane * 2;
#pragma unroll 2
        for (int kt = 0; kt < KT_P2; kt++) {
            unsigned a[4][4];
#pragma unroll
            for (int m = 0; m < 4; m++) ldA<516>(a[m], XA + m * 16 * 516, kt, g, t);
#pragma unroll
            for (int i = 0; i < 2; i++) {
                uint2 b = *(const uint2*)(bbase + (size_t)i * KT_P2 * 64 + kt * 64);
#pragma unroll
                for (int m = 0; m < 4; m++) mma8(C2[m][i], a[m], b.x, b.y);
            }
        }
    }
#pragma unroll
    for (int m = 0; m < 4; m++)
#pragma unroll
        for (int i = 0; i < 2; i++) {
            const int j0 = 16 * warp + i * 8 + 2 * t;
            float* y0 = out + Y_OFF + (rowBase + m * 16 + g) * NYY;
            float* y1 = out + Y_OFF + (rowBase + m * 16 + g + 8) * NYY;
            y0[j0]     = C2[m][i][0] + bp2[j0];
            y0[j0 + 1] = C2[m][i][1] + bp2[j0 + 1];
            y1[j0]     = C2[m][i][2] + bp2[j0];
            y1[j0 + 1] = C2[m][i][3] + bp2[j0 + 1];
        }
}

extern "C" void kernel_launch(void* const* d_in, const int* in_sizes, int n_in,
                              void* d_out, int out_size) {
    // dict/signature order: Y0, [Nhrzn,] Wq,bq, Wp1,bp1, Wp2,bp2,
    //                       Wl1,bl1, Wl2,bl2, W_ih,W_hh, b_ih,b_hh
    int off = (n_in >= 16 && in_sizes[1] == 1) ? 2 : 1;
    const float* Y0  = (const float*)d_in[0];
    const float* Wq  = (const float*)d_in[off + 0];
    const float* bq  = (const float*)d_in[off + 1];
    const float* Wp1 = (const float*)d_in[off + 2];
    const float* bp1 = (const float*)d_in[off + 3];
    const float* Wp2 = (const float*)d_in[off + 4];
    const float* bp2 = (const float*)d_in[off + 5];
    const float* Wl1 = (const float*)d_in[off + 6];
    const float* bl1 = (const float*)d_in[off + 7];
    const float* Wl2 = (const float*)d_in[off + 8];
    const float* bl2 = (const float*)d_in[off + 9];
    const float* Wih = (const float*)d_in[off + 10];
    const float* Whh = (const float*)d_in[off + 11];
    const float* bih = (const float*)d_in[off + 12];
    const float* bhh = (const float*)d_in[off + 13];
    float* out = (float*)d_out;

    cudaFuncSetAttribute(recur_kernel, cudaFuncAttributeMaxDynamicSharedMemorySize,
                         SMEM_UNITS * 4);
    cudaFuncSetAttribute(proj_kernel, cudaFuncAttributeMaxDynamicSharedMemorySize,
                         PROJ_SMEM_UNITS * 4);

    pack_kernel<<<128, 256>>>(Wq, Wl1, Wl2, Wih, Whh, Wp1, Wp2);
    recur_kernel<<<NCTA, 512, SMEM_UNITS * 4>>>(Y0, bq, bl1, bl2, bih, bhh, out);
    proj_kernel<<<(TT * NB) / PROJ_ROWS, 512, PROJ_SMEM_UNITS * 4>>>(bp1, bp2, out);
}

// round 12
// speedup vs baseline: 8.2471x; 1.0826x over previous
#include <cuda_runtime.h>
#include <math.h>

#define NXX   512
#define NWW   512
#define NYY   256
#define NWUP  128
#define NB    1024
#define NHR   32
#define TT    (NWUP + 1 + NHR)          // 161

#define X_SIZE   ((size_t)TT * NB * NXX)
#define L_OFF    (X_SIZE)
#define L_SIZE   ((size_t)NWUP * NB * NWW)
#define Y_OFF    (L_OFF + L_SIZE)

// recurrence: 32 clusters x 4 CTAs; cluster owns 32 rows; CTA computes N/4.
#define CROWS 32
#define NCTA  128

// ---- packed tf32 weight buffers (B-fragment order) ----
#define KT_WQ 32
#define KT_L1 96
#define KT_L2 64
#define KT_RZ 128
#define KT_NI 64
#define KT_NH 64
#define KT_P1 64
#define KT_P2 64
#define OFF_WQ 0
#define SZ_WQ  (64 * KT_WQ * 64)
#define OFF_L1 (OFF_WQ + SZ_WQ)
#define SZ_L1  (64 * KT_L1 * 64)
#define OFF_L2 (OFF_L1 + SZ_L1)
#define SZ_L2  (64 * KT_L2 * 64)
#define OFF_RZ (OFF_L2 + SZ_L2)
#define SZ_RZ  (128 * KT_RZ * 64)
#define OFF_NI (OFF_RZ + SZ_RZ)
#define SZ_NI  (64 * KT_NI * 64)
#define OFF_NH (OFF_NI + SZ_NI)
#define SZ_NH  (64 * KT_NH * 64)
#define OFF_P1 (OFF_NH + SZ_NH)
#define SZ_P1  (64 * KT_P1 * 64)
#define OFF_P2 (OFF_P1 + SZ_P1)
#define SZ_P2  (32 * KT_P2 * 64)
#define WPACK_TOTAL (OFF_P2 + SZ_P2)

__device__ unsigned g_wpack[WPACK_TOTAL];

// ---- recurrence smem: ACT [32][1284] tf32 (w/l1: 0-511, h: 512-1023, y: 1024-1279)
//      + HF [32][132] fp32 (local quarter of h) ----
#define AST     1284
#define HF_OFF  (CROWS * AST)            // 41,088
#define SMEM_UNITS (HF_OFF + CROWS * 132)   // 45,312 u32 = 181,248 B

// ---- proj smem: [64][516] tf32 ----
#define PROJ_ROWS 64
#define PROJ_SMEM_UNITS (PROJ_ROWS * 516)

__device__ __forceinline__ float sigm(float x) { return 1.0f / (1.0f + expf(-x)); }

__device__ __forceinline__ unsigned f2tf32(float x) {
    unsigned u;
    asm("cvt.rna.tf32.f32 %0, %1;" : "=r"(u) : "f"(x));
    return u;
}

__device__ __forceinline__ void mma8(float c[4], const unsigned a[4],
                                     unsigned b0, unsigned b1) {
    asm("mma.sync.aligned.m16n8k8.row.col.f32.tf32.tf32.f32 "
        "{%0,%1,%2,%3},{%4,%5,%6,%7},{%8,%9},{%0,%1,%2,%3};"
        : "+f"(c[0]), "+f"(c[1]), "+f"(c[2]), "+f"(c[3])
        : "r"(a[0]), "r"(a[1]), "r"(a[2]), "r"(a[3]), "r"(b0), "r"(b1));
}

__device__ __forceinline__ void cbar() {
    asm volatile("barrier.cluster.arrive.aligned;" ::: "memory");
    asm volatile("barrier.cluster.wait.aligned;" ::: "memory");
}

// JAX partitionable threefry bits: counter (0, i), key (0,1), bits = x0 ^ x1.
__device__ __forceinline__ float frand_sign(unsigned i) {
    const unsigned ks0 = 0u, ks1 = 1u, ks2 = 0x1BD11BDBu;
    unsigned x0 = 0u + ks0;
    unsigned x1 = i  + ks1;
#define QR4(RA,RB,RC,RD) \
    x0 += x1; x1 = __funnelshift_l(x1, x1, RA); x1 ^= x0; \
    x0 += x1; x1 = __funnelshift_l(x1, x1, RB); x1 ^= x0; \
    x0 += x1; x1 = __funnelshift_l(x1, x1, RC); x1 ^= x0; \
    x0 += x1; x1 = __funnelshift_l(x1, x1, RD); x1 ^= x0;
    QR4(13,15,26, 6)  x0 += ks1; x1 += ks2 + 1u;
    QR4(17,29,16,24)  x0 += ks2; x1 += ks0 + 2u;
    QR4(13,15,26, 6)  x0 += ks0; x1 += ks1 + 3u;
    QR4(17,29,16,24)  x0 += ks1; x1 += ks2 + 4u;
    QR4(13,15,26, 6)  x0 += ks2; x1 += ks0 + 5u;
#undef QR4
    return ((x0 ^ x1) & 0x80000000u) ? -1.0f : 1.0f;
}

// ---------------------------------------------------------------------------
// Weight packing (verbatim from R11).
// ---------------------------------------------------------------------------
__device__ void packSeg(unsigned* dst, const float* S1, int ld1,
                        const float* S2, int ld2, int ksplit,
                        int N, int KTl, int tid, int nth) {
    const int tot = (N / 8) * KTl * 32;
    for (int p = tid; p < tot; p += nth) {
        const int lane = p & 31, kt = (p >> 5) % KTl, nt = (p >> 5) / KTl;
        const int g = lane >> 2, t = lane & 3;
        const int n = nt * 8 + g;
        const int k0 = kt * 8 + t, k1 = k0 + 4;
        float v0 = (k0 < ksplit) ? S1[(size_t)n * ld1 + k0] : S2[(size_t)n * ld2 + (k0 - ksplit)];
        float v1 = (k1 < ksplit) ? S1[(size_t)n * ld1 + k1] : S2[(size_t)n * ld2 + (k1 - ksplit)];
        dst[(size_t)p * 2]     = f2tf32(v0);
        dst[(size_t)p * 2 + 1] = f2tf32(v1);
    }
}

__global__ void pack_kernel(const float* __restrict__ Wq,  const float* __restrict__ Wl1,
                            const float* __restrict__ Wl2, const float* __restrict__ Wih,
                            const float* __restrict__ Whh, const float* __restrict__ Wp1,
                            const float* __restrict__ Wp2) {
    const int tid = blockIdx.x * blockDim.x + threadIdx.x;
    const int nth = gridDim.x * blockDim.x;
    packSeg(g_wpack + OFF_WQ, Wq, 256, Wq, 256, 256, 512, KT_WQ, tid, nth);
    packSeg(g_wpack + OFF_L1, Wl1, 768, Wl1, 768, 768, 512, KT_L1, tid, nth);
    packSeg(g_wpack + OFF_L2, Wl2, 512, Wl2, 512, 512, 512, KT_L2, tid, nth);
    packSeg(g_wpack + OFF_RZ, Wih, 512, Whh, 512, 512, 1024, KT_RZ, tid, nth);  // [w|h] K-fused
    packSeg(g_wpack + OFF_NI, Wih + 1024 * 512, 512, Wih, 512, 512, 512, KT_NI, tid, nth);
    packSeg(g_wpack + OFF_NH, Whh + 1024 * 512, 512, Whh, 512, 512, 512, KT_NH, tid, nth);
    packSeg(g_wpack + OFF_P1, Wp1, 512, Wp1, 512, 512, 512, KT_P1, tid, nth);
    packSeg(g_wpack + OFF_P2, Wp2, 512, Wp2, 512, 512, 256, KT_P2, tid, nth);
}

// A-fragment load (m16n8k8 tf32)
template<int STRIDE>
__device__ __forceinline__ void ldA(unsigned a[4], const unsigned* As, int kt, int g, int t) {
    const unsigned* p = As + g * STRIDE + kt * 8 + t;
    a[0] = p[0];
    a[1] = p[8 * STRIDE];
    a[2] = p[4];
    a[3] = p[8 * STRIDE + 4];
}

// Quarter-GEMM for recurrence: NT n-tiles, M=32 (2 m-tiles), A from ACT (stride 1284)
template<int NT, int KTL>
__device__ __forceinline__ void gemmQ(float C[][2][4], const unsigned* __restrict__ Bp,
                                      const int* tiles, const unsigned* As,
                                      int lane, int g, int t) {
    const unsigned* bptr[NT];
#pragma unroll
    for (int i = 0; i < NT; i++)
        bptr[i] = Bp + (size_t)tiles[i] * KTL * 64 + lane * 2;
#pragma unroll 4
    for (int kt = 0; kt < KTL; kt++) {
        unsigned a0[4], a1[4];
        ldA<AST>(a0, As, kt, g, t);
        ldA<AST>(a1, As + 16 * AST, kt, g, t);
#pragma unroll
        for (int i = 0; i < NT; i++) {
            uint2 b = *(const uint2*)(bptr[i] + kt * 64);
            mma8(C[i][0], a0, b.x, b.y);
            mma8(C[i][1], a1, b.x, b.y);
        }
    }
}

#define ZC3(C, n) float C[n][2][4]; \
    _Pragma("unroll") for (int _i = 0; _i < n; _i++) \
    _Pragma("unroll") for (int _m = 0; _m < 2; _m++) { \
        C[_i][_m][0] = 0.f; C[_i][_m][1] = 0.f; C[_i][_m][2] = 0.f; C[_i][_m][3] = 0.f; }

// ---------------------------------------------------------------------------
// Persistent recurrence: 32 clusters x 4 CTAs x 512 threads, 32 rows/cluster.
// ---------------------------------------------------------------------------
__global__ void __launch_bounds__(512, 1) __cluster_dims__(4, 1, 1) recur_kernel(
    const float* __restrict__ Y0,
    const float* __restrict__ bq,
    const float* __restrict__ bl1, const float* __restrict__ bl2,
    const float* __restrict__ bih, const float* __restrict__ bhh,
    float* __restrict__ out)
{
    extern __shared__ unsigned smemU[];
    float* hFp = (float*)(smemU + HF_OFF);

    const int tid  = threadIdx.x;
    const int warp = tid >> 5, lane = tid & 31;
    const int g = lane >> 2, t = lane & 3;
    const int rank    = blockIdx.x & 3;
    const int rowBase = (blockIdx.x >> 2) * CROWS;
    const int jg0 = 128 * rank + 8 * warp + 2 * t;  // this thread's even global col
    const int jl0 = 8 * warp + 2 * t;               // local hF col

    unsigned sbase = (unsigned)__cvta_generic_to_shared(smemU);
    unsigned peerBase[4];
#pragma unroll
    for (int rk = 0; rk < 4; rk++)
        asm("mapa.shared::cluster.u32 %0, %1, %2;" : "=r"(peerBase[rk]) : "r"(sbase), "r"(rk));

    // store tf32 pair (col jc, jc+1) of ACT row into ALL 4 cluster CTAs
    auto putA4 = [&](int row, int jc, unsigned u0, unsigned u1) {
        const unsigned off = 4u * (unsigned)(row * AST + jc);
        const unsigned long long pv = (unsigned long long)u0 | ((unsigned long long)u1 << 32);
#pragma unroll
        for (int rk = 0; rk < 4; rk++)
            asm volatile("st.shared::cluster.u64 [%0], %1;"
                         :: "r"(peerBase[rk] + off), "l"(pv) : "memory");
    };

    int tl1[1]  = {16 * rank + warp};
    int tlrz[2] = {16 * rank + warp, 64 + 16 * rank + warp};

    // ---- x0 = tanh(Y0[0] @ Wq.T + bq) ----
    for (int i = tid; i < CROWS * 256; i += 512) {
        const int r = i >> 8, cl = i & 255;
        smemU[r * AST + 1024 + cl] = f2tf32(Y0[(size_t)(rowBase + r) * NYY + cl]);
    }
    cbar();   // y ready locally everywhere; peers alive before first DSMEM write
    {
        ZC3(Cq, 1);
        gemmQ<1, KT_WQ>(Cq, g_wpack + OFF_WQ, tl1, smemU + 1024, lane, g, t);
#pragma unroll
        for (int m = 0; m < 2; m++) {
            const int r0 = m * 16 + g, r1 = r0 + 8;
            const float h00 = tanhf(Cq[0][m][0] + bq[jg0]);
            const float h01 = tanhf(Cq[0][m][1] + bq[jg0 + 1]);
            const float h10 = tanhf(Cq[0][m][2] + bq[jg0]);
            const float h11 = tanhf(Cq[0][m][3] + bq[jg0 + 1]);
            hFp[r0 * 132 + jl0] = h00; hFp[r0 * 132 + jl0 + 1] = h01;
            hFp[r1 * 132 + jl0] = h10; hFp[r1 * 132 + jl0 + 1] = h11;
            putA4(r0, 512 + jg0, f2tf32(h00), f2tf32(h01));
            putA4(r1, 512 + jg0, f2tf32(h10), f2tf32(h11));
            *(float2*)(out + (size_t)(rowBase + r0) * NXX + jg0) = make_float2(h00, h01);
            *(float2*)(out + (size_t)(rowBase + r1) * NXX + jg0) = make_float2(h10, h11);
        }
    }
    cbar();   // h0 visible everywhere

    // ---- 160 sequential steps ----
    for (int tstep = 0; tstep < NWUP + NHR; tstep++) {
        if (tstep < NWUP) {
            // y = Y0[t+1] -> local ACT.y
            for (int i = tid; i < CROWS * 256; i += 512) {
                const int r = i >> 8, cl = i & 255;
                smemU[r * AST + 1024 + cl] =
                    f2tf32(Y0[((size_t)(tstep + 1) * NB + rowBase + r) * NYY + cl]);
            }
            __syncthreads();

            // l1 = tanh([h|y] @ Wl1.T + bl1) -> ACT cols [0,512) of all ranks
            {
                ZC3(C, 1);
                gemmQ<1, KT_L1>(C, g_wpack + OFF_L1, tl1, smemU + 512, lane, g, t);
#pragma unroll
                for (int m = 0; m < 2; m++) {
                    const int r0 = m * 16 + g, r1 = r0 + 8;
                    putA4(r0, jg0, f2tf32(tanhf(C[0][m][0] + bl1[jg0])),
                                   f2tf32(tanhf(C[0][m][1] + bl1[jg0 + 1])));
                    putA4(r1, jg0, f2tf32(tanhf(C[0][m][2] + bl1[jg0])),
                                   f2tf32(tanhf(C[0][m][3] + bl1[jg0 + 1])));
                }
            }
            cbar();   // B1: l1 complete cluster-wide

            // logit = l1 @ Wl2.T + bl2 -> gmem ; w = tanh(0.5*logit) -> ACT[0,512)
            {
                ZC3(C, 1);
                gemmQ<1, KT_L2>(C, g_wpack + OFF_L2, tl1, smemU, lane, g, t);
                cbar();   // B2: l1 consumed cluster-wide (before overwrite with w)
                float* lb = out + L_OFF + ((size_t)tstep * NB + rowBase) * NWW;
#pragma unroll
                for (int m = 0; m < 2; m++) {
                    const int r0 = m * 16 + g, r1 = r0 + 8;
                    const float lg00 = C[0][m][0] + bl2[jg0];
                    const float lg01 = C[0][m][1] + bl2[jg0 + 1];
                    const float lg10 = C[0][m][2] + bl2[jg0];
                    const float lg11 = C[0][m][3] + bl2[jg0 + 1];
                    *(float2*)(lb + (size_t)r0 * NWW + jg0) = make_float2(lg00, lg01);
                    *(float2*)(lb + (size_t)r1 * NWW + jg0) = make_float2(lg10, lg11);
                    putA4(r0, jg0, f2tf32(tanhf(0.5f * lg00)), f2tf32(tanhf(0.5f * lg01)));
                    putA4(r1, jg0, f2tf32(tanhf(0.5f * lg10)), f2tf32(tanhf(0.5f * lg11)));
                }
            }
            cbar();   // B3: w ready everywhere
        } else {
            // free-run: each CTA computes full-width w locally (no exchange)
            const unsigned tf = (unsigned)(tstep - NWUP);
            for (int i = tid; i < CROWS * 512; i += 512) {
                const int r = i >> 9, j = i & 511;
                const unsigned idx = (((unsigned)tf * NB + (unsigned)(rowBase + r)) << 9) + (unsigned)j;
                smemU[r * AST + j] = __float_as_uint(frand_sign(idx));
            }
            __syncthreads();
        }

        // ---- GRU quarter GEMMs (local reads only) ----
        ZC3(Crz, 2);
        gemmQ<2, KT_RZ>(Crz, g_wpack + OFF_RZ, tlrz, smemU, lane, g, t);
        ZC3(Cni, 1);
        gemmQ<1, KT_NI>(Cni, g_wpack + OFF_NI, tl1, smemU, lane, g, t);
        ZC3(Cnh, 1);
        gemmQ<1, KT_NH>(Cnh, g_wpack + OFF_NH, tl1, smemU + 512, lane, g, t);
        cbar();   // B4: all reads of h/w done cluster-wide

        // ---- h update (thread owns cols jg0, jg0+1) ----
        float* xb = out + ((size_t)(tstep + 1) * NB + rowBase) * NXX;
#pragma unroll
        for (int m = 0; m < 2; m++) {
            const int r0 = m * 16 + g, r1 = r0 + 8;
            float hva[2], hvb[2];
#pragma unroll
            for (int cc = 0; cc < 2; cc++) {
                const int jg = jg0 + cc;
                const float br  = bih[jg] + bhh[jg];
                const float bz  = bih[jg + 512] + bhh[jg + 512];
                const float bi3 = bih[jg + 1024], bh3 = bhh[jg + 1024];
                {
                    const float rv = sigm(Crz[0][m][cc] + br);
                    const float zv = sigm(Crz[1][m][cc] + bz);
                    const float nv = tanhf(Cni[0][m][cc] + bi3 + rv * (Cnh[0][m][cc] + bh3));
                    const float ho = hFp[r0 * 132 + jl0 + cc];
                    const float hv = (1.0f - zv) * nv + zv * ho;
                    hFp[r0 * 132 + jl0 + cc] = hv;
                    hva[cc] = hv;
                }
                {
                    const float rv = sigm(Crz[0][m][2 + cc] + br);
                    const float zv = sigm(Crz[1][m][2 + cc] + bz);
                    const float nv = tanhf(Cni[0][m][2 + cc] + bi3 + rv * (Cnh[0][m][2 + cc] + bh3));
                    const float ho = hFp[r1 * 132 + jl0 + cc];
                    const float hv = (1.0f - zv) * nv + zv * ho;
                    hFp[r1 * 132 + jl0 + cc] = hv;
                    hvb[cc] = hv;
                }
            }
            putA4(r0, 512 + jg0, f2tf32(hva[0]), f2tf32(hva[1]));
            putA4(r1, 512 + jg0, f2tf32(hvb[0]), f2tf32(hvb[1]));
            *(float2*)(xb + (size_t)r0 * NXX + jg0) = make_float2(hva[0], hva[1]);
            *(float2*)(xb + (size_t)r1 * NXX + jg0) = make_float2(hvb[0], hvb[1]);
        }
        cbar();   // B5: h ready everywhere
    }
}

// ---------------------------------------------------------------------------
// proj (verbatim from passing R11): Yhat = tanh(X @ Wp1.T + bp1) @ Wp2.T + bp2
// ---------------------------------------------------------------------------
__global__ void __launch_bounds__(512, 1) proj_kernel(
    const float* __restrict__ bp1, const float* __restrict__ bp2,
    float* __restrict__ out)
{
    extern __shared__ unsigned XA[];     // [64][516] tf32
    const int tid = threadIdx.x, warp = tid >> 5, lane = tid & 31;
    const int g = lane >> 2, t = lane & 3;
    const size_t rowBase = (size_t)blockIdx.x * PROJ_ROWS;

    for (int i = tid; i < PROJ_ROWS * 512; i += 512) {
        const int r = i >> 9, cl = i & 511;
        XA[r * 516 + cl] = f2tf32(out[(rowBase + r) * NXX + cl]);
    }
    __syncthreads();

    float C[4][4][4];
#pragma unroll
    for (int m = 0; m < 4; m++)
#pragma unroll
        for (int i = 0; i < 4; i++) { C[m][i][0]=0.f; C[m][i][1]=0.f; C[m][i][2]=0.f; C[m][i][3]=0.f; }
    {
        const unsigned* bbase = g_wpack + OFF_P1 + (size_t)(4 * warp) * KT_P1 * 64 + lane * 2;
#pragma unroll 2
        for (int kt = 0; kt < KT_P1; kt++) {
            unsigned a[4][4];
#pragma unroll
            for (int m = 0; m < 4; m++) ldA<516>(a[m], XA + m * 16 * 516, kt, g, t);
#pragma unroll
            for (int i = 0; i < 4; i++) {
                uint2 b = *(const uint2*)(bbase + (size_t)i * KT_P1 * 64 + kt * 64);
#pragma unroll
                for (int m = 0; m < 4; m++) mma8(C[m][i], a[m], b.x, b.y);
            }
        }
    }
    __syncthreads();
#pragma unroll
    for (int m = 0; m < 4; m++)
#pragma unroll
        for (int i = 0; i < 4; i++) {
            const int j0 = 32 * warp + i * 8 + 2 * t;
            XA[(m * 16 + g) * 516 + j0]         = f2tf32(tanhf(C[m][i][0] + bp1[j0]));
            XA[(m * 16 + g) * 516 + j0 + 1]     = f2tf32(tanhf(C[m][i][1] + bp1[j0 + 1]));
            XA[(m * 16 + g + 8) * 516 + j0]     = f2tf32(tanhf(C[m][i][2] + bp1[j0]));
            XA[(m * 16 + g + 8) * 516 + j0 + 1] = f2tf32(tanhf(C[m][i][3] + bp1[j0 + 1]));
        }
    __syncthreads();

    float C2[4][2][4];
#pragma unroll
    for (int m = 0; m < 4; m++)
#pragma unroll
        for (int i = 0; i < 2; i++) { C2[m][i][0]=0.f; C2[m][i][1]=0.f; C2[m][i][2]=0.f; C2[m][i][3]=0.f; }
    {
        const unsigned* bbase = g_wpack + OFF_P2 + (size_t)(2 * warp) * KT_P2 * 64 + lane * 2;
#pragma unroll 2
        for (int kt = 0; kt < KT_P2; kt++) {
            unsigned a[4][4];
#pragma unroll
            for (int m = 0; m < 4; m++) ldA<516>(a[m], XA + m * 16 * 516, kt, g, t);
#pragma unroll
            for (int i = 0; i < 2; i++) {
                uint2 b = *(const uint2*)(bbase + (size_t)i * KT_P2 * 64 + kt * 64);
#pragma unroll
                for (int m = 0; m < 4; m++) mma8(C2[m][i], a[m], b.x, b.y);
            }
        }
    }
#pragma unroll
    for (int m = 0; m < 4; m++)
#pragma unroll
        for (int i = 0; i < 2; i++) {
            const int j0 = 16 * warp + i * 8 + 2 * t;
            float* y0 = out + Y_OFF + (rowBase + m * 16 + g) * NYY;
            float* y1 = out + Y_OFF + (rowBase + m * 16 + g + 8) * NYY;
            y0[j0]     = C2[m][i][0] + bp2[j0];
            y0[j0 + 1] = C2[m][i][1] + bp2[j0 + 1];
            y1[j0]     = C2[m][i][2] + bp2[j0];
            y1[j0 + 1] = C2[m][i][3] + bp2[j0 + 1];
        }
}

extern "C" void kernel_launch(void* const* d_in, const int* in_sizes, int n_in,
                              void* d_out, int out_size) {
    // dict/signature order: Y0, [Nhrzn,] Wq,bq, Wp1,bp1, Wp2,bp2,
    //                       Wl1,bl1, Wl2,bl2, W_ih,W_hh, b_ih,b_hh
    int off = (n_in >= 16 && in_sizes[1] == 1) ? 2 : 1;
    const float* Y0  = (const float*)d_in[0];
    const float* Wq  = (const float*)d_in[off + 0];
    const float* bq  = (const float*)d_in[off + 1];
    const float* Wp1 = (const float*)d_in[off + 2];
    const float* bp1 = (const float*)d_in[off + 3];
    const float* Wp2 = (const float*)d_in[off + 4];
    const float* bp2 = (const float*)d_in[off + 5];
    const float* Wl1 = (const float*)d_in[off + 6];
    const float* bl1 = (const float*)d_in[off + 7];
    const float* Wl2 = (const float*)d_in[off + 8];
    const float* bl2 = (const float*)d_in[off + 9];
    const float* Wih = (const float*)d_in[off + 10];
    const float* Whh = (const float*)d_in[off + 11];
    const float* bih = (const float*)d_in[off + 12];
    const float* bhh = (const float*)d_in[off + 13];
    float* out = (float*)d_out;

    cudaFuncSetAttribute(recur_kernel, cudaFuncAttributeMaxDynamicSharedMemorySize,
                         SMEM_UNITS * 4);
    cudaFuncSetAttribute(proj_kernel, cudaFuncAttributeMaxDynamicSharedMemorySize,
                         PROJ_SMEM_UNITS * 4);

    pack_kernel<<<128, 256>>>(Wq, Wl1, Wl2, Wih, Whh, Wp1, Wp2);
    recur_kernel<<<NCTA, 512, SMEM_UNITS * 4>>>(Y0, bq, bl1, bl2, bih, bhh, out);
    proj_kernel<<<(TT * NB) / PROJ_ROWS, 512, PROJ_SMEM_UNITS * 4>>>(bp1, bp2, out);
}

// round 13
// speedup vs baseline: 8.6559x; 1.0496x over previous
#include <cuda_runtime.h>
#include <math.h>

#define NXX   512
#define NWW   512
#define NYY   256
#define NWUP  128
#define NB    1024
#define NHR   32
#define TT    (NWUP + 1 + NHR)          // 161

#define X_SIZE   ((size_t)TT * NB * NXX)
#define L_OFF    (X_SIZE)
#define L_SIZE   ((size_t)NWUP * NB * NWW)
#define Y_OFF    (L_OFF + L_SIZE)

// recurrence: 32 clusters x 4 CTAs; cluster owns 32 rows; CTA computes N/4.
#define CROWS 32
#define NCTA  128

// ---- packed tf32 weight buffers (B-fragment order) ----
#define KT_WQ 32
#define KT_L1 96
#define KT_L2 64
#define KT_RZ 128
#define KT_NI 64
#define KT_NH 64
#define KT_P1 64
#define KT_P2 64
#define OFF_WQ 0
#define SZ_WQ  (64 * KT_WQ * 64)
#define OFF_L1 (OFF_WQ + SZ_WQ)
#define SZ_L1  (64 * KT_L1 * 64)
#define OFF_L2 (OFF_L1 + SZ_L1)
#define SZ_L2  (64 * KT_L2 * 64)
#define OFF_RZ (OFF_L2 + SZ_L2)
#define SZ_RZ  (128 * KT_RZ * 64)
#define OFF_NI (OFF_RZ + SZ_RZ)
#define SZ_NI  (64 * KT_NI * 64)
#define OFF_NH (OFF_NI + SZ_NI)
#define SZ_NH  (64 * KT_NH * 64)
#define OFF_P1 (OFF_NH + SZ_NH)
#define SZ_P1  (64 * KT_P1 * 64)
#define OFF_P2 (OFF_P1 + SZ_P1)
#define SZ_P2  (32 * KT_P2 * 64)
#define WPACK_TOTAL (OFF_P2 + SZ_P2)

__device__ unsigned g_wpack[WPACK_TOTAL];

// ---- recurrence smem: ACT [32][1284] tf32 (w/l1: 0-511, h: 512-1023, y: 1024-1279)
//      + HF [32][132] fp32 (local quarter of h) ----
#define AST     1284
#define HF_OFF  (CROWS * AST)
#define SMEM_UNITS (HF_OFF + CROWS * 132)   // 45,312 u32 = 181,248 B

// ---- proj smem: [64][516] tf32 ----
#define PROJ_ROWS 64
#define PROJ_SMEM_UNITS (PROJ_ROWS * 516)

__device__ __forceinline__ float sigm(float x) { return 1.0f / (1.0f + expf(-x)); }

__device__ __forceinline__ unsigned f2tf32(float x) {
    unsigned u;
    asm("cvt.rna.tf32.f32 %0, %1;" : "=r"(u) : "f"(x));
    return u;
}

__device__ __forceinline__ void mma8(float c[4], const unsigned a[4],
                                     unsigned b0, unsigned b1) {
    asm("mma.sync.aligned.m16n8k8.row.col.f32.tf32.tf32.f32 "
        "{%0,%1,%2,%3},{%4,%5,%6,%7},{%8,%9},{%0,%1,%2,%3};"
        : "+f"(c[0]), "+f"(c[1]), "+f"(c[2]), "+f"(c[3])
        : "r"(a[0]), "r"(a[1]), "r"(a[2]), "r"(a[3]), "r"(b0), "r"(b1));
}

__device__ __forceinline__ void cbar() {
    asm volatile("barrier.cluster.arrive.aligned;" ::: "memory");
    asm volatile("barrier.cluster.wait.aligned;" ::: "memory");
}

// JAX partitionable threefry bits: counter (0, i), key (0,1), bits = x0 ^ x1.
__device__ __forceinline__ float frand_sign(unsigned i) {
    const unsigned ks0 = 0u, ks1 = 1u, ks2 = 0x1BD11BDBu;
    unsigned x0 = 0u + ks0;
    unsigned x1 = i  + ks1;
#define QR4(RA,RB,RC,RD) \
    x0 += x1; x1 = __funnelshift_l(x1, x1, RA); x1 ^= x0; \
    x0 += x1; x1 = __funnelshift_l(x1, x1, RB); x1 ^= x0; \
    x0 += x1; x1 = __funnelshift_l(x1, x1, RC); x1 ^= x0; \
    x0 += x1; x1 = __funnelshift_l(x1, x1, RD); x1 ^= x0;
    QR4(13,15,26, 6)  x0 += ks1; x1 += ks2 + 1u;
    QR4(17,29,16,24)  x0 += ks2; x1 += ks0 + 2u;
    QR4(13,15,26, 6)  x0 += ks0; x1 += ks1 + 3u;
    QR4(17,29,16,24)  x0 += ks1; x1 += ks2 + 4u;
    QR4(13,15,26, 6)  x0 += ks2; x1 += ks0 + 5u;
#undef QR4
    return ((x0 ^ x1) & 0x80000000u) ? -1.0f : 1.0f;
}

// ---------------------------------------------------------------------------
// Weight packing (verbatim).
// ---------------------------------------------------------------------------
__device__ void packSeg(unsigned* dst, const float* S1, int ld1,
                        const float* S2, int ld2, int ksplit,
                        int N, int KTl, int tid, int nth) {
    const int tot = (N / 8) * KTl * 32;
    for (int p = tid; p < tot; p += nth) {
        const int lane = p & 31, kt = (p >> 5) % KTl, nt = (p >> 5) / KTl;
        const int g = lane >> 2, t = lane & 3;
        const int n = nt * 8 + g;
        const int k0 = kt * 8 + t, k1 = k0 + 4;
        float v0 = (k0 < ksplit) ? S1[(size_t)n * ld1 + k0] : S2[(size_t)n * ld2 + (k0 - ksplit)];
        float v1 = (k1 < ksplit) ? S1[(size_t)n * ld1 + k1] : S2[(size_t)n * ld2 + (k1 - ksplit)];
        dst[(size_t)p * 2]     = f2tf32(v0);
        dst[(size_t)p * 2 + 1] = f2tf32(v1);
    }
}

__global__ void pack_kernel(const float* __restrict__ Wq,  const float* __restrict__ Wl1,
                            const float* __restrict__ Wl2, const float* __restrict__ Wih,
                            const float* __restrict__ Whh, const float* __restrict__ Wp1,
                            const float* __restrict__ Wp2) {
    const int tid = blockIdx.x * blockDim.x + threadIdx.x;
    const int nth = gridDim.x * blockDim.x;
    packSeg(g_wpack + OFF_WQ, Wq, 256, Wq, 256, 256, 512, KT_WQ, tid, nth);
    packSeg(g_wpack + OFF_L1, Wl1, 768, Wl1, 768, 768, 512, KT_L1, tid, nth);
    packSeg(g_wpack + OFF_L2, Wl2, 512, Wl2, 512, 512, 512, KT_L2, tid, nth);
    packSeg(g_wpack + OFF_RZ, Wih, 512, Whh, 512, 512, 1024, KT_RZ, tid, nth);
    packSeg(g_wpack + OFF_NI, Wih + 1024 * 512, 512, Wih, 512, 512, 512, KT_NI, tid, nth);
    packSeg(g_wpack + OFF_NH, Whh + 1024 * 512, 512, Whh, 512, 512, 512, KT_NH, tid, nth);
    packSeg(g_wpack + OFF_P1, Wp1, 512, Wp1, 512, 512, 512, KT_P1, tid, nth);
    packSeg(g_wpack + OFF_P2, Wp2, 512, Wp2, 512, 512, 256, KT_P2, tid, nth);
}

// A-fragment load (m16n8k8 tf32)
template<int STRIDE>
__device__ __forceinline__ void ldA(unsigned a[4], const unsigned* As, int kt, int g, int t) {
    const unsigned* p = As + g * STRIDE + kt * 8 + t;
    a[0] = p[0];
    a[1] = p[8 * STRIDE];
    a[2] = p[4];
    a[3] = p[8 * STRIDE + 4];
}

// Single-m-tile quarter GEMM: warp covers one 16-row m-tile, NT n-tiles.
template<int NT, int KTL>
__device__ __forceinline__ void gemmQ1(float C[][4], const unsigned* __restrict__ Bp,
                                       const int* tiles, const unsigned* As,
                                       int lane, int g, int t) {
    const unsigned* bptr[NT];
#pragma unroll
    for (int i = 0; i < NT; i++)
        bptr[i] = Bp + (size_t)tiles[i] * KTL * 64 + lane * 2;
#pragma unroll 4
    for (int kt = 0; kt < KTL; kt++) {
        unsigned a[4];
        ldA<AST>(a, As, kt, g, t);
#pragma unroll
        for (int i = 0; i < NT; i++) {
            uint2 b = *(const uint2*)(bptr[i] + kt * 64);
            mma8(C[i], a, b.x, b.y);
        }
    }
}

#define ZC2(C, n) float C[n][4]; \
    _Pragma("unroll") for (int _i = 0; _i < n; _i++) { \
        C[_i][0] = 0.f; C[_i][1] = 0.f; C[_i][2] = 0.f; C[_i][3] = 0.f; }

// ---------------------------------------------------------------------------
// Persistent recurrence: 32 clusters x 4 CTAs x 512 threads, 32 rows/cluster.
// Warp mapping: mt = warp>>3 selects m-tile (16 rows); w8 = warp&7 covers
// 2 n-tiles of each 128-col quarter (4 n-tiles for rz).
// ---------------------------------------------------------------------------
__global__ void __launch_bounds__(512, 1) __cluster_dims__(4, 1, 1) recur_kernel(
    const float* __restrict__ Y0,
    const float* __restrict__ bq,
    const float* __restrict__ bl1, const float* __restrict__ bl2,
    const float* __restrict__ bih, const float* __restrict__ bhh,
    float* __restrict__ out)
{
    extern __shared__ unsigned smemU[];
    float* hFp = (float*)(smemU + HF_OFF);

    const int tid  = threadIdx.x;
    const int warp = tid >> 5, lane = tid & 31;
    const int g = lane >> 2, t = lane & 3;
    const int mt = warp >> 3, w8 = warp & 7;
    const int rank    = blockIdx.x & 3;
    const int rowBase = (blockIdx.x >> 2) * CROWS;
    const int r0 = mt * 16 + g, r1 = r0 + 8;          // this warp's rows
    const unsigned* Amt = smemU + mt * 16 * AST;      // m-tile A base

    unsigned sbase = (unsigned)__cvta_generic_to_shared(smemU);
    unsigned peerBase[4];
#pragma unroll
    for (int rk = 0; rk < 4; rk++)
        asm("mapa.shared::cluster.u32 %0, %1, %2;" : "=r"(peerBase[rk]) : "r"(sbase), "r"(rk));

    auto putA4 = [&](int row, int jc, unsigned u0, unsigned u1) {
        const unsigned off = 4u * (unsigned)(row * AST + jc);
        const unsigned long long pv = (unsigned long long)u0 | ((unsigned long long)u1 << 32);
#pragma unroll
        for (int rk = 0; rk < 4; rk++)
            asm volatile("st.shared::cluster.u64 [%0], %1;"
                         :: "r"(peerBase[rk] + off), "l"(pv) : "memory");
    };

    const int T1 = 16 * rank + 2 * w8;
    int tl2[2] = {T1, T1 + 1};
    int tl4[4] = {T1, T1 + 1, 64 + T1, 64 + T1 + 1};
    // column bases for the 2 owned n-tiles
    const int jgA = 128 * rank + 2 * w8 * 8 + 2 * t;      // n-tile i=0
    const int jlA = 2 * w8 * 8 + 2 * t;                   // local hF col, i=0

    // ---- x0 = tanh(Y0[0] @ Wq.T + bq) ----
    for (int i = tid; i < CROWS * 256; i += 512) {
        const int r = i >> 8, cl = i & 255;
        smemU[r * AST + 1024 + cl] = f2tf32(Y0[(size_t)(rowBase + r) * NYY + cl]);
    }
    cbar();
    {
        ZC2(Cq, 2);
        gemmQ1<2, KT_WQ>(Cq, g_wpack + OFF_WQ, tl2, Amt + 1024, lane, g, t);
#pragma unroll
        for (int i = 0; i < 2; i++) {
            const int jg = jgA + i * 8, jl = jlA + i * 8;
            const float h00 = tanhf(Cq[i][0] + bq[jg]);
            const float h01 = tanhf(Cq[i][1] + bq[jg + 1]);
            const float h10 = tanhf(Cq[i][2] + bq[jg]);
            const float h11 = tanhf(Cq[i][3] + bq[jg + 1]);
            hFp[r0 * 132 + jl] = h00; hFp[r0 * 132 + jl + 1] = h01;
            hFp[r1 * 132 + jl] = h10; hFp[r1 * 132 + jl + 1] = h11;
            putA4(r0, 512 + jg, f2tf32(h00), f2tf32(h01));
            putA4(r1, 512 + jg, f2tf32(h10), f2tf32(h11));
            *(float2*)(out + (size_t)(rowBase + r0) * NXX + jg) = make_float2(h00, h01);
            *(float2*)(out + (size_t)(rowBase + r1) * NXX + jg) = make_float2(h10, h11);
        }
    }
    cbar();

    // ---- 160 sequential steps ----
    for (int tstep = 0; tstep < NWUP + NHR; tstep++) {
        if (tstep < NWUP) {
            for (int i = tid; i < CROWS * 256; i += 512) {
                const int r = i >> 8, cl = i & 255;
                smemU[r * AST + 1024 + cl] =
                    f2tf32(Y0[((size_t)(tstep + 1) * NB + rowBase + r) * NYY + cl]);
            }
            __syncthreads();

            // l1 = tanh([h|y] @ Wl1.T + bl1) -> ACT[0,512) of all ranks
            {
                ZC2(C, 2);
                gemmQ1<2, KT_L1>(C, g_wpack + OFF_L1, tl2, Amt + 512, lane, g, t);
#pragma unroll
                for (int i = 0; i < 2; i++) {
                    const int jg = jgA + i * 8;
                    putA4(r0, jg, f2tf32(tanhf(C[i][0] + bl1[jg])),
                                  f2tf32(tanhf(C[i][1] + bl1[jg + 1])));
                    putA4(r1, jg, f2tf32(tanhf(C[i][2] + bl1[jg])),
                                  f2tf32(tanhf(C[i][3] + bl1[jg + 1])));
                }
            }
            cbar();   // B1: l1 complete cluster-wide

            // logit = l1 @ Wl2.T + bl2 -> gmem ; w = tanh(0.5*logit) -> ACT[0,512)
            {
                ZC2(C, 2);
                gemmQ1<2, KT_L2>(C, g_wpack + OFF_L2, tl2, Amt, lane, g, t);
                cbar();   // B2: l1 consumed before overwrite with w
                float* lb = out + L_OFF + ((size_t)tstep * NB + rowBase) * NWW;
#pragma unroll
                for (int i = 0; i < 2; i++) {
                    const int jg = jgA + i * 8;
                    const float lg00 = C[i][0] + bl2[jg];
                    const float lg01 = C[i][1] + bl2[jg + 1];
                    const float lg10 = C[i][2] + bl2[jg];
                    const float lg11 = C[i][3] + bl2[jg + 1];
                    *(float2*)(lb + (size_t)r0 * NWW + jg) = make_float2(lg00, lg01);
                    *(float2*)(lb + (size_t)r1 * NWW + jg) = make_float2(lg10, lg11);
                    putA4(r0, jg, f2tf32(tanhf(0.5f * lg00)), f2tf32(tanhf(0.5f * lg01)));
                    putA4(r1, jg, f2tf32(tanhf(0.5f * lg10)), f2tf32(tanhf(0.5f * lg11)));
                }
            }
            cbar();   // B3: w ready everywhere
        } else {
            const unsigned tf = (unsigned)(tstep - NWUP);
            for (int i = tid; i < CROWS * 512; i += 512) {
                const int r = i >> 9, j = i & 511;
                const unsigned idx = (((unsigned)tf * NB + (unsigned)(rowBase + r)) << 9) + (unsigned)j;
                smemU[r * AST + j] = __float_as_uint(frand_sign(idx));
            }
            __syncthreads();
        }

        // ---- GRU quarter GEMMs (local reads only) ----
        ZC2(Crz, 4);
        gemmQ1<4, KT_RZ>(Crz, g_wpack + OFF_RZ, tl4, Amt, lane, g, t);
        ZC2(Cni, 2);
        gemmQ1<2, KT_NI>(Cni, g_wpack + OFF_NI, tl2, Amt, lane, g, t);
        ZC2(Cnh, 2);
        gemmQ1<2, KT_NH>(Cnh, g_wpack + OFF_NH, tl2, Amt + 512, lane, g, t);
        cbar();   // B4: all reads of h/w done cluster-wide

        // ---- h update (warp owns rows r0,r1; cols of its 2 n-tiles) ----
        float* xb = out + ((size_t)(tstep + 1) * NB + rowBase) * NXX;
#pragma unroll
        for (int i = 0; i < 2; i++) {
            const int jg0 = jgA + i * 8, jl0 = jlA + i * 8;
            float hva[2], hvb[2];
#pragma unroll
            for (int cc = 0; cc < 2; cc++) {
                const int jg = jg0 + cc;
                const float br  = bih[jg] + bhh[jg];
                const float bz  = bih[jg + 512] + bhh[jg + 512];
                const float bi3 = bih[jg + 1024], bh3 = bhh[jg + 1024];
                {
                    const float rv = sigm(Crz[i][cc] + br);
                    const float zv = sigm(Crz[2 + i][cc] + bz);
                    const float nv = tanhf(Cni[i][cc] + bi3 + rv * (Cnh[i][cc] + bh3));
                    const float ho = hFp[r0 * 132 + jl0 + cc];
                    const float hv = (1.0f - zv) * nv + zv * ho;
                    hFp[r0 * 132 + jl0 + cc] = hv;
                    hva[cc] = hv;
                }
                {
                    const float rv = sigm(Crz[i][2 + cc] + br);
                    const float zv = sigm(Crz[2 + i][2 + cc] + bz);
                    const float nv = tanhf(Cni[i][2 + cc] + bi3 + rv * (Cnh[i][2 + cc] + bh3));
                    const float ho = hFp[r1 * 132 + jl0 + cc];
                    const float hv = (1.0f - zv) * nv + zv * ho;
                    hFp[r1 * 132 + jl0 + cc] = hv;
                    hvb[cc] = hv;
                }
            }
            putA4(r0, 512 + jg0, f2tf32(hva[0]), f2tf32(hva[1]));
            putA4(r1, 512 + jg0, f2tf32(hvb[0]), f2tf32(hvb[1]));
            *(float2*)(xb + (size_t)r0 * NXX + jg0) = make_float2(hva[0], hva[1]);
            *(float2*)(xb + (size_t)r1 * NXX + jg0) = make_float2(hvb[0], hvb[1]);
        }
        cbar();   // B5: h ready everywhere
    }
}

// ---------------------------------------------------------------------------
// proj (verbatim from passing R11/R12)
// ---------------------------------------------------------------------------
__global__ void __launch_bounds__(512, 1) proj_kernel(
    const float* __restrict__ bp1, const float* __restrict__ bp2,
    float* __restrict__ out)
{
    extern __shared__ unsigned XA[];     // [64][516] tf32
    const int tid = threadIdx.x, warp = tid >> 5, lane = tid & 31;
    const int g = lane >> 2, t = lane & 3;
    const size_t rowBase = (size_t)blockIdx.x * PROJ_ROWS;

    for (int i = tid; i < PROJ_ROWS * 512; i += 512) {
        const int r = i >> 9, cl = i & 511;
        XA[r * 516 + cl] = f2tf32(out[(rowBase + r) * NXX + cl]);
    }
    __syncthreads();

    float C[4][4][4];
#pragma unroll
    for (int m = 0; m < 4; m++)
#pragma unroll
        for (int i = 0; i < 4; i++) { C[m][i][0]=0.f; C[m][i][1]=0.f; C[m][i][2]=0.f; C[m][i][3]=0.f; }
    {
        const unsigned* bbase = g_wpack + OFF_P1 + (size_t)(4 * warp) * KT_P1 * 64 + lane * 2;
#pragma unroll 2
        for (int kt = 0; kt < KT_P1; kt++) {
            unsigned a[4][4];
#pragma unroll
            for (int m = 0; m < 4; m++) {
                const unsigned* p = XA + (m * 16 + g) * 516 + kt * 8 + t;
                a[m][0] = p[0]; a[m][1] = p[8 * 516]; a[m][2] = p[4]; a[m][3] = p[8 * 516 + 4];
            }
#pragma unroll
            for (int i = 0; i < 4; i++) {
                uint2 b = *(const uint2*)(bbase + (size_t)i * KT_P1 * 64 + kt * 64);
#pragma unroll
                for (int m = 0; m < 4; m++) mma8(C[m][i], a[m], b.x, b.y);
            }
        }
    }
    __syncthreads();
#pragma unroll
    for (int m = 0; m < 4; m++)
#pragma unroll
        for (int i = 0; i < 4; i++) {
            const int j0 = 32 * warp + i * 8 + 2 * t;
            XA[(m * 16 + g) * 516 + j0]         = f2tf32(tanhf(C[m][i][0] + bp1[j0]));
            XA[(m * 16 + g) * 516 + j0 + 1]     = f2tf32(tanhf(C[m][i][1] + bp1[j0 + 1]));
            XA[(m * 16 + g + 8) * 516 + j0]     = f2tf32(tanhf(C[m][i][2] + bp1[j0]));
            XA[(m * 16 + g + 8) * 516 + j0 + 1] = f2tf32(tanhf(C[m][i][3] + bp1[j0 + 1]));
        }
    __syncthreads();

    float C2[4][2][4];
#pragma unroll
    for (int m = 0; m < 4; m++)
#pragma unroll
        for (int i = 0; i < 2; i++) { C2[m][i][0]=0.f; C2[m][i][1]=0.f; C2[m][i][2]=0.f; C2[m][i][3]=0.f; }
    {
        const unsigned* bbase = g_wpack + OFF_P2 + (size_t)(2 * warp) * KT_P2 * 64 + lane * 2;
#pragma unroll 2
        for (int kt = 0; kt < KT_P2; kt++) {
            unsigned a[4][4];
#pragma unroll
            for (int m = 0; m < 4; m++) {
                const unsigned* p = XA + (m * 16 + g) * 516 + kt * 8 + t;
                a[m][0] = p[0]; a[m][1] = p[8 * 516]; a[m][2] = p[4]; a[m][3] = p[8 * 516 + 4];
            }
#pragma unroll
            for (int i = 0; i < 2; i++) {
                uint2 b = *(const uint2*)(bbase + (size_t)i * KT_P2 * 64 + kt * 64);
#pragma unroll
                for (int m = 0; m < 4; m++) mma8(C2[m][i], a[m], b.x, b.y);
            }
        }
    }
#pragma unroll
    for (int m = 0; m < 4; m++)
#pragma unroll
        for (int i = 0; i < 2; i++) {
            const int j0 = 16 * warp + i * 8 + 2 * t;
            float* y0 = out + Y_OFF + (rowBase + m * 16 + g) * NYY;
            float* y1 = out + Y_OFF + (rowBase + m * 16 + g + 8) * NYY;
            y0[j0]     = C2[m][i][0] + bp2[j0];
            y0[j0 + 1] = C2[m][i][1] + bp2[j0 + 1];
            y1[j0]     = C2[m][i][2] + bp2[j0];
            y1[j0 + 1] = C2[m][i][3] + bp2[j0 + 1];
        }
}

extern "C" void kernel_launch(void* const* d_in, const int* in_sizes, int n_in,
                              void* d_out, int out_size) {
    int off = (n_in >= 16 && in_sizes[1] == 1) ? 2 : 1;
    const float* Y0  = (const float*)d_in[0];
    const float* Wq  = (const float*)d_in[off + 0];
    const float* bq  = (const float*)d_in[off + 1];
    const float* Wp1 = (const float*)d_in[off + 2];
    const float* bp1 = (const float*)d_in[off + 3];
    const float* Wp2 = (const float*)d_in[off + 4];
    const float* bp2 = (const float*)d_in[off + 5];
    const float* Wl1 = (const float*)d_in[off + 6];
    const float* bl1 = (const float*)d_in[off + 7];
    const float* Wl2 = (const float*)d_in[off + 8];
    const float* bl2 = (const float*)d_in[off + 9];
    const float* Wih = (const float*)d_in[off + 10];
    const float* Whh = (const float*)d_in[off + 11];
    const float* bih = (const float*)d_in[off + 12];
    const float* bhh = (const float*)d_in[off + 13];
    float* out = (float*)d_out;

    cudaFuncSetAttribute(recur_kernel, cudaFuncAttributeMaxDynamicSharedMemorySize,
                         SMEM_UNITS * 4);
    cudaFuncSetAttribute(proj_kernel, cudaFuncAttributeMaxDynamicSharedMemorySize,
                         PROJ_SMEM_UNITS * 4);

    pack_kernel<<<128, 256>>>(Wq, Wl1, Wl2, Wih, Whh, Wp1, Wp2);
    recur_kernel<<<NCTA, 512, SMEM_UNITS * 4>>>(Y0, bq, bl1, bl2, bih, bhh, out);
    proj_kernel<<<(TT * NB) / PROJ_ROWS, 512, PROJ_SMEM_UNITS * 4>>>(bp1, bp2, out);
}

// round 14
// speedup vs baseline: 9.6192x; 1.1113x over previous
#include <cuda_runtime.h>
#include <math.h>

#define NXX   512
#define NWW   512
#define NYY   256
#define NWUP  128
#define NB    1024
#define NHR   32
#define TT    (NWUP + 1 + NHR)          // 161

#define X_SIZE   ((size_t)TT * NB * NXX)
#define L_OFF    (X_SIZE)
#define L_SIZE   ((size_t)NWUP * NB * NWW)
#define Y_OFF    (L_OFF + L_SIZE)

// recurrence: 32 clusters x 4 CTAs; cluster owns 32 rows; CTA computes N/4.
#define CROWS 32
#define NCTA  128

// ---- packed tf32 weight buffers (pair-interleaved B-fragment order) ----
#define KT_WQ 32
#define KT_L1 96
#define KT_L2 64
#define KT_RZ 128
#define KT_NI 64
#define KT_NH 64
#define KT_P1 64
#define KT_P2 64
#define OFF_WQ 0
#define SZ_WQ  (64 * KT_WQ * 64)
#define OFF_L1 (OFF_WQ + SZ_WQ)
#define SZ_L1  (64 * KT_L1 * 64)
#define OFF_L2 (OFF_L1 + SZ_L1)
#define SZ_L2  (64 * KT_L2 * 64)
#define OFF_RZ (OFF_L2 + SZ_L2)
#define SZ_RZ  (128 * KT_RZ * 64)
#define OFF_NI (OFF_RZ + SZ_RZ)
#define SZ_NI  (64 * KT_NI * 64)
#define OFF_NH (OFF_NI + SZ_NI)
#define SZ_NH  (64 * KT_NH * 64)
#define OFF_P1 (OFF_NH + SZ_NH)
#define SZ_P1  (64 * KT_P1 * 64)
#define OFF_P2 (OFF_P1 + SZ_P1)
#define SZ_P2  (32 * KT_P2 * 64)
#define WPACK_TOTAL (OFF_P2 + SZ_P2)

__device__ unsigned g_wpack[WPACK_TOTAL];

// ---- recurrence smem: ACT [32][1284] tf32 (w/l1: 0-511, h: 512-1023, y: 1024-1279)
//      + HF [32][132] fp32 ----
#define AST     1284
#define HF_OFF  (CROWS * AST)
#define SMEM_UNITS (HF_OFF + CROWS * 132)   // 181,248 B

// ---- proj smem: [64][516] tf32 ----
#define PROJ_ROWS 64
#define PROJ_SMEM_UNITS (PROJ_ROWS * 516)

__device__ __forceinline__ float sigm(float x) { return 1.0f / (1.0f + expf(-x)); }

__device__ __forceinline__ unsigned f2tf32(float x) {
    unsigned u;
    asm("cvt.rna.tf32.f32 %0, %1;" : "=r"(u) : "f"(x));
    return u;
}

__device__ __forceinline__ void mma8(float c[4], const unsigned a[4],
                                     unsigned b0, unsigned b1) {
    asm("mma.sync.aligned.m16n8k8.row.col.f32.tf32.tf32.f32 "
        "{%0,%1,%2,%3},{%4,%5,%6,%7},{%8,%9},{%0,%1,%2,%3};"
        : "+f"(c[0]), "+f"(c[1]), "+f"(c[2]), "+f"(c[3])
        : "r"(a[0]), "r"(a[1]), "r"(a[2]), "r"(a[3]), "r"(b0), "r"(b1));
}

__device__ __forceinline__ void cbar() {
    asm volatile("barrier.cluster.arrive.aligned;" ::: "memory");
    asm volatile("barrier.cluster.wait.aligned;" ::: "memory");
}

// JAX partitionable threefry bits: counter (0, i), key (0,1), bits = x0 ^ x1.
__device__ __forceinline__ float frand_sign(unsigned i) {
    const unsigned ks0 = 0u, ks1 = 1u, ks2 = 0x1BD11BDBu;
    unsigned x0 = 0u + ks0;
    unsigned x1 = i  + ks1;
#define QR4(RA,RB,RC,RD) \
    x0 += x1; x1 = __funnelshift_l(x1, x1, RA); x1 ^= x0; \
    x0 += x1; x1 = __funnelshift_l(x1, x1, RB); x1 ^= x0; \
    x0 += x1; x1 = __funnelshift_l(x1, x1, RC); x1 ^= x0; \
    x0 += x1; x1 = __funnelshift_l(x1, x1, RD); x1 ^= x0;
    QR4(13,15,26, 6)  x0 += ks1; x1 += ks2 + 1u;
    QR4(17,29,16,24)  x0 += ks2; x1 += ks0 + 2u;
    QR4(13,15,26, 6)  x0 += ks0; x1 += ks1 + 3u;
    QR4(17,29,16,24)  x0 += ks1; x1 += ks2 + 4u;
    QR4(13,15,26, 6)  x0 += ks2; x1 += ks0 + 5u;
#undef QR4
    return ((x0 ^ x1) & 0x80000000u) ? -1.0f : 1.0f;
}

// ---------------------------------------------------------------------------
// Weight packing: pair-interleaved fragments. For n-tile nt, kt-pair kp,
// lane l: words [kt=2kp b0,b1, kt=2kp+1 b0,b1] at nt*KTl*64 + kp*128 + l*4.
// ---------------------------------------------------------------------------
__device__ void packSeg(unsigned* dst, const float* S1, int ld1,
                        const float* S2, int ld2, int ksplit,
                        int N, int KTl, int tid, int nth) {
    const int tot = (N / 8) * KTl * 32;
    for (int p = tid; p < tot; p += nth) {
        const int lane = p & 31, kt = (p >> 5) % KTl, nt = (p >> 5) / KTl;
        const int g = lane >> 2, t = lane & 3;
        const int n = nt * 8 + g;
        const int k0 = kt * 8 + t, k1 = k0 + 4;
        float v0 = (k0 < ksplit) ? S1[(size_t)n * ld1 + k0] : S2[(size_t)n * ld2 + (k0 - ksplit)];
        float v1 = (k1 < ksplit) ? S1[(size_t)n * ld1 + k1] : S2[(size_t)n * ld2 + (k1 - ksplit)];
        const int kp = kt >> 1, half = kt & 1;
        unsigned* q = dst + ((size_t)nt * KTl * 64 + (size_t)kp * 128 + lane * 4 + half * 2);
        q[0] = f2tf32(v0);
        q[1] = f2tf32(v1);
    }
}

__global__ void pack_kernel(const float* __restrict__ Wq,  const float* __restrict__ Wl1,
                            const float* __restrict__ Wl2, const float* __restrict__ Wih,
                            const float* __restrict__ Whh, const float* __restrict__ Wp1,
                            const float* __restrict__ Wp2) {
    const int tid = blockIdx.x * blockDim.x + threadIdx.x;
    const int nth = gridDim.x * blockDim.x;
    packSeg(g_wpack + OFF_WQ, Wq, 256, Wq, 256, 256, 512, KT_WQ, tid, nth);
    packSeg(g_wpack + OFF_L1, Wl1, 768, Wl1, 768, 768, 512, KT_L1, tid, nth);
    packSeg(g_wpack + OFF_L2, Wl2, 512, Wl2, 512, 512, 512, KT_L2, tid, nth);
    packSeg(g_wpack + OFF_RZ, Wih, 512, Whh, 512, 512, 1024, KT_RZ, tid, nth);
    packSeg(g_wpack + OFF_NI, Wih + 1024 * 512, 512, Wih, 512, 512, 512, KT_NI, tid, nth);
    packSeg(g_wpack + OFF_NH, Whh + 1024 * 512, 512, Whh, 512, 512, 512, KT_NH, tid, nth);
    packSeg(g_wpack + OFF_P1, Wp1, 512, Wp1, 512, 512, 512, KT_P1, tid, nth);
    packSeg(g_wpack + OFF_P2, Wp2, 512, Wp2, 512, 512, 256, KT_P2, tid, nth);
}

// A-fragment load (m16n8k8 tf32)
template<int STRIDE>
__device__ __forceinline__ void ldA(unsigned a[4], const unsigned* As, int kt, int g, int t) {
    const unsigned* p = As + g * STRIDE + kt * 8 + t;
    a[0] = p[0];
    a[1] = p[8 * STRIDE];
    a[2] = p[4];
    a[3] = p[8 * STRIDE + 4];
}

// Single-m-tile quarter GEMM with uint4 B loads (2 kt per load).
template<int NT, int KTL>
__device__ __forceinline__ void gemmP(float C[][4], const unsigned* __restrict__ Bp,
                                      const int* tiles, const unsigned* As,
                                      int lane, int g, int t) {
    const unsigned* bptr[NT];
#pragma unroll
    for (int i = 0; i < NT; i++)
        bptr[i] = Bp + (size_t)tiles[i] * KTL * 64 + lane * 4;
#pragma unroll 2
    for (int kp = 0; kp < KTL / 2; kp++) {
        unsigned a0[4], a1[4];
        ldA<AST>(a0, As, 2 * kp, g, t);
        ldA<AST>(a1, As, 2 * kp + 1, g, t);
#pragma unroll
        for (int i = 0; i < NT; i++) {
            uint4 b = *(const uint4*)(bptr[i] + (size_t)kp * 128);
            mma8(C[i], a0, b.x, b.y);
            mma8(C[i], a1, b.z, b.w);
        }
    }
}

#define ZC2(C, n) float C[n][4]; \
    _Pragma("unroll") for (int _i = 0; _i < n; _i++) { \
        C[_i][0] = 0.f; C[_i][1] = 0.f; C[_i][2] = 0.f; C[_i][3] = 0.f; }

// ---------------------------------------------------------------------------
// Persistent recurrence: 32 clusters x 4 CTAs x 512 threads, 32 rows/cluster.
// ---------------------------------------------------------------------------
__global__ void __launch_bounds__(512, 1) __cluster_dims__(4, 1, 1) recur_kernel(
    const float* __restrict__ Y0,
    const float* __restrict__ bq,
    const float* __restrict__ bl1, const float* __restrict__ bl2,
    const float* __restrict__ bih, const float* __restrict__ bhh,
    float* __restrict__ out)
{
    extern __shared__ unsigned smemU[];
    float* hFp = (float*)(smemU + HF_OFF);

    const int tid  = threadIdx.x;
    const int warp = tid >> 5, lane = tid & 31;
    const int g = lane >> 2, t = lane & 3;
    const int mt = warp >> 3, w8 = warp & 7;
    const int rank    = blockIdx.x & 3;
    const int rowBase = (blockIdx.x >> 2) * CROWS;
    const int r0 = mt * 16 + g, r1 = r0 + 8;
    const unsigned* Amt = smemU + mt * 16 * AST;

    unsigned sbase = (unsigned)__cvta_generic_to_shared(smemU);
    unsigned peerBase[4];
#pragma unroll
    for (int rk = 0; rk < 4; rk++)
        asm("mapa.shared::cluster.u32 %0, %1, %2;" : "=r"(peerBase[rk]) : "r"(sbase), "r"(rk));

    auto putA4 = [&](int row, int jc, unsigned u0, unsigned u1) {
        const unsigned off = 4u * (unsigned)(row * AST + jc);
        const unsigned long long pv = (unsigned long long)u0 | ((unsigned long long)u1 << 32);
#pragma unroll
        for (int rk = 0; rk < 4; rk++)
            asm volatile("st.shared::cluster.u64 [%0], %1;"
                         :: "r"(peerBase[rk] + off), "l"(pv) : "memory");
    };

    const int T1 = 16 * rank + 2 * w8;
    int tl2[2] = {T1, T1 + 1};
    int tl4[4] = {T1, T1 + 1, 64 + T1, 64 + T1 + 1};
    const int jgA = 128 * rank + 2 * w8 * 8 + 2 * t;
    const int jlA = 2 * w8 * 8 + 2 * t;

    // ---- x0 = tanh(Y0[0] @ Wq.T + bq) ----
    for (int i = tid; i < CROWS * 256; i += 512) {
        const int r = i >> 8, cl = i & 255;
        smemU[r * AST + 1024 + cl] = f2tf32(Y0[(size_t)(rowBase + r) * NYY + cl]);
    }
    cbar();
    {
        ZC2(Cq, 2);
        gemmP<2, KT_WQ>(Cq, g_wpack + OFF_WQ, tl2, Amt + 1024, lane, g, t);
#pragma unroll
        for (int i = 0; i < 2; i++) {
            const int jg = jgA + i * 8, jl = jlA + i * 8;
            const float h00 = tanhf(Cq[i][0] + bq[jg]);
            const float h01 = tanhf(Cq[i][1] + bq[jg + 1]);
            const float h10 = tanhf(Cq[i][2] + bq[jg]);
            const float h11 = tanhf(Cq[i][3] + bq[jg + 1]);
            hFp[r0 * 132 + jl] = h00; hFp[r0 * 132 + jl + 1] = h01;
            hFp[r1 * 132 + jl] = h10; hFp[r1 * 132 + jl + 1] = h11;
            putA4(r0, 512 + jg, f2tf32(h00), f2tf32(h01));
            putA4(r1, 512 + jg, f2tf32(h10), f2tf32(h11));
            *(float2*)(out + (size_t)(rowBase + r0) * NXX + jg) = make_float2(h00, h01);
            *(float2*)(out + (size_t)(rowBase + r1) * NXX + jg) = make_float2(h10, h11);
        }
    }
    cbar();

    // ---- 160 sequential steps ----
    for (int tstep = 0; tstep < NWUP + NHR; tstep++) {
        if (tstep < NWUP) {
            for (int i = tid; i < CROWS * 256; i += 512) {
                const int r = i >> 8, cl = i & 255;
                smemU[r * AST + 1024 + cl] =
                    f2tf32(Y0[((size_t)(tstep + 1) * NB + rowBase + r) * NYY + cl]);
            }
            __syncthreads();

            // l1 = tanh([h|y] @ Wl1.T + bl1) -> ACT[0,512) of all ranks
            {
                ZC2(C, 2);
                gemmP<2, KT_L1>(C, g_wpack + OFF_L1, tl2, Amt + 512, lane, g, t);
#pragma unroll
                for (int i = 0; i < 2; i++) {
                    const int jg = jgA + i * 8;
                    putA4(r0, jg, f2tf32(tanhf(C[i][0] + bl1[jg])),
                                  f2tf32(tanhf(C[i][1] + bl1[jg + 1])));
                    putA4(r1, jg, f2tf32(tanhf(C[i][2] + bl1[jg])),
                                  f2tf32(tanhf(C[i][3] + bl1[jg + 1])));
                }
            }
            cbar();   // B1: l1 complete cluster-wide

            // logit = l1 @ Wl2.T + bl2 -> gmem ; w = tanh(0.5*logit) -> ACT[0,512)
            {
                ZC2(C, 2);
                gemmP<2, KT_L2>(C, g_wpack + OFF_L2, tl2, Amt, lane, g, t);
                cbar();   // B2: l1 consumed before overwrite with w
                float* lb = out + L_OFF + ((size_t)tstep * NB + rowBase) * NWW;
#pragma unroll
                for (int i = 0; i < 2; i++) {
                    const int jg = jgA + i * 8;
                    const float lg00 = C[i][0] + bl2[jg];
                    const float lg01 = C[i][1] + bl2[jg + 1];
                    const float lg10 = C[i][2] + bl2[jg];
                    const float lg11 = C[i][3] + bl2[jg + 1];
                    *(float2*)(lb + (size_t)r0 * NWW + jg) = make_float2(lg00, lg01);
                    *(float2*)(lb + (size_t)r1 * NWW + jg) = make_float2(lg10, lg11);
                    putA4(r0, jg, f2tf32(tanhf(0.5f * lg00)), f2tf32(tanhf(0.5f * lg01)));
                    putA4(r1, jg, f2tf32(tanhf(0.5f * lg10)), f2tf32(tanhf(0.5f * lg11)));
                }
            }
            cbar();   // B3: w ready everywhere
        } else {
            const unsigned tf = (unsigned)(tstep - NWUP);
            for (int i = tid; i < CROWS * 512; i += 512) {
                const int r = i >> 9, j = i & 511;
                const unsigned idx = (((unsigned)tf * NB + (unsigned)(rowBase + r)) << 9) + (unsigned)j;
                smemU[r * AST + j] = __float_as_uint(frand_sign(idx));
            }
            __syncthreads();
        }

        // ---- merged GRU GEMMs: rz + ni + nh in one loop (high MLP) ----
        ZC2(Crz, 4); ZC2(Cni, 2); ZC2(Cnh, 2);
        {
            const unsigned* brz[4];
            const unsigned* bni[2];
            const unsigned* bnh[2];
#pragma unroll
            for (int i = 0; i < 4; i++)
                brz[i] = g_wpack + OFF_RZ + (size_t)tl4[i] * KT_RZ * 64 + lane * 4;
#pragma unroll
            for (int i = 0; i < 2; i++) {
                bni[i] = g_wpack + OFF_NI + (size_t)tl2[i] * KT_NI * 64 + lane * 4;
                bnh[i] = g_wpack + OFF_NH + (size_t)tl2[i] * KT_NH * 64 + lane * 4;
            }
#pragma unroll 2
            for (int kp = 0; kp < 32; kp++) {
                unsigned aw0[4], aw1[4], ah0[4], ah1[4];
                ldA<AST>(aw0, Amt, 2 * kp, g, t);
                ldA<AST>(aw1, Amt, 2 * kp + 1, g, t);
                ldA<AST>(ah0, Amt + 512, 2 * kp, g, t);
                ldA<AST>(ah1, Amt + 512, 2 * kp + 1, g, t);
#pragma unroll
                for (int i = 0; i < 4; i++) {
                    uint4 b = *(const uint4*)(brz[i] + (size_t)kp * 128);
                    mma8(Crz[i], aw0, b.x, b.y);
                    mma8(Crz[i], aw1, b.z, b.w);
                    uint4 b2 = *(const uint4*)(brz[i] + (size_t)(kp + 32) * 128);
                    mma8(Crz[i], ah0, b2.x, b2.y);
                    mma8(Crz[i], ah1, b2.z, b2.w);
                }
#pragma unroll
                for (int i = 0; i < 2; i++) {
                    uint4 b = *(const uint4*)(bni[i] + (size_t)kp * 128);
                    mma8(Cni[i], aw0, b.x, b.y);
                    mma8(Cni[i], aw1, b.z, b.w);
                    uint4 c = *(const uint4*)(bnh[i] + (size_t)kp * 128);
                    mma8(Cnh[i], ah0, c.x, c.y);
                    mma8(Cnh[i], ah1, c.z, c.w);
                }
            }
        }
        cbar();   // B4: all reads of h/w done cluster-wide

        // ---- h update ----
        float* xb = out + ((size_t)(tstep + 1) * NB + rowBase) * NXX;
#pragma unroll
        for (int i = 0; i < 2; i++) {
            const int jg0 = jgA + i * 8, jl0 = jlA + i * 8;
            float hva[2], hvb[2];
#pragma unroll
            for (int cc = 0; cc < 2; cc++) {
                const int jg = jg0 + cc;
                const float br  = bih[jg] + bhh[jg];
                const float bz  = bih[jg + 512] + bhh[jg + 512];
                const float bi3 = bih[jg + 1024], bh3 = bhh[jg + 1024];
                {
                    const float rv = sigm(Crz[i][cc] + br);
                    const float zv = sigm(Crz[2 + i][cc] + bz);
                    const float nv = tanhf(Cni[i][cc] + bi3 + rv * (Cnh[i][cc] + bh3));
                    const float ho = hFp[r0 * 132 + jl0 + cc];
                    const float hv = (1.0f - zv) * nv + zv * ho;
                    hFp[r0 * 132 + jl0 + cc] = hv;
                    hva[cc] = hv;
                }
                {
                    const float rv = sigm(Crz[i][2 + cc] + br);
                    const float zv = sigm(Crz[2 + i][2 + cc] + bz);
                    const float nv = tanhf(Cni[i][2 + cc] + bi3 + rv * (Cnh[i][2 + cc] + bh3));
                    const float ho = hFp[r1 * 132 + jl0 + cc];
                    const float hv = (1.0f - zv) * nv + zv * ho;
                    hFp[r1 * 132 + jl0 + cc] = hv;
                    hvb[cc] = hv;
                }
            }
            putA4(r0, 512 + jg0, f2tf32(hva[0]), f2tf32(hva[1]));
            putA4(r1, 512 + jg0, f2tf32(hvb[0]), f2tf32(hvb[1]));
            *(float2*)(xb + (size_t)r0 * NXX + jg0) = make_float2(hva[0], hva[1]);
            *(float2*)(xb + (size_t)r1 * NXX + jg0) = make_float2(hvb[0], hvb[1]);
        }
        cbar();   // B5: h ready everywhere
    }
}

// ---------------------------------------------------------------------------
// proj: Yhat = tanh(X @ Wp1.T + bp1) @ Wp2.T + bp2   (uint4 B loads)
// ---------------------------------------------------------------------------
__global__ void __launch_bounds__(512, 1) proj_kernel(
    const float* __restrict__ bp1, const float* __restrict__ bp2,
    float* __restrict__ out)
{
    extern __shared__ unsigned XA[];     // [64][516] tf32
    const int tid = threadIdx.x, warp = tid >> 5, lane = tid & 31;
    const int g = lane >> 2, t = lane & 3;
    const size_t rowBase = (size_t)blockIdx.x * PROJ_ROWS;

    for (int i = tid; i < PROJ_ROWS * 512; i += 512) {
        const int r = i >> 9, cl = i & 511;
        XA[r * 516 + cl] = f2tf32(out[(rowBase + r) * NXX + cl]);
    }
    __syncthreads();

    float C[4][4][4];
#pragma unroll
    for (int m = 0; m < 4; m++)
#pragma unroll
        for (int i = 0; i < 4; i++) { C[m][i][0]=0.f; C[m][i][1]=0.f; C[m][i][2]=0.f; C[m][i][3]=0.f; }
    {
        const unsigned* bbase = g_wpack + OFF_P1 + (size_t)(4 * warp) * KT_P1 * 64 + lane * 4;
#pragma unroll 1
        for (int kp = 0; kp < KT_P1 / 2; kp++) {
            unsigned a0[4][4], a1[4][4];
#pragma unroll
            for (int m = 0; m < 4; m++) {
                ldA<516>(a0[m], XA + m * 16 * 516, 2 * kp, g, t);
                ldA<516>(a1[m], XA + m * 16 * 516, 2 * kp + 1, g, t);
            }
#pragma unroll
            for (int i = 0; i < 4; i++) {
                uint4 b = *(const uint4*)(bbase + (size_t)i * KT_P1 * 64 + (size_t)kp * 128);
#pragma unroll
                for (int m = 0; m < 4; m++) {
                    mma8(C[m][i], a0[m], b.x, b.y);
                    mma8(C[m][i], a1[m], b.z, b.w);
                }
            }
        }
    }
    __syncthreads();
#pragma unroll
    for (int m = 0; m < 4; m++)
#pragma unroll
        for (int i = 0; i < 4; i++) {
            const int j0 = 32 * warp + i * 8 + 2 * t;
            XA[(m * 16 + g) * 516 + j0]         = f2tf32(tanhf(C[m][i][0] + bp1[j0]));
            XA[(m * 16 + g) * 516 + j0 + 1]     = f2tf32(tanhf(C[m][i][1] + bp1[j0 + 1]));
            XA[(m * 16 + g + 8) * 516 + j0]     = f2tf32(tanhf(C[m][i][2] + bp1[j0]));
            XA[(m * 16 + g + 8) * 516 + j0 + 1] = f2tf32(tanhf(C[m][i][3] + bp1[j0 + 1]));
        }
    __syncthreads();

    float C2[4][2][4];
#pragma unroll
    for (int m = 0; m < 4; m++)
#pragma unroll
        for (int i = 0; i < 2; i++) { C2[m][i][0]=0.f; C2[m][i][1]=0.f; C2[m][i][2]=0.f; C2[m][i][3]=0.f; }
    {
        const unsigned* bbase = g_wpack + OFF_P2 + (size_t)(2 * warp) * KT_P2 * 64 + lane * 4;
#pragma unroll 1
        for (int kp = 0; kp < KT_P2 / 2; kp++) {
            unsigned a0[4][4], a1[4][4];
#pragma unroll
            for (int m = 0; m < 4; m++) {
                ldA<516>(a0[m], XA + m * 16 * 516, 2 * kp, g, t);
                ldA<516>(a1[m], XA + m * 16 * 516, 2 * kp + 1, g, t);
            }
#pragma unroll
            for (int i = 0; i < 2; i++) {
                uint4 b = *(const uint4*)(bbase + (size_t)i * KT_P2 * 64 + (size_t)kp * 128);
#pragma unroll
                for (int m = 0; m < 4; m++) {
                    mma8(C2[m][i], a0[m], b.x, b.y);
                    mma8(C2[m][i], a1[m], b.z, b.w);
                }
            }
        }
    }
#pragma unroll
    for (int m = 0; m < 4; m++)
#pragma unroll
        for (int i = 0; i < 2; i++) {
            const int j0 = 16 * warp + i * 8 + 2 * t;
            float* y0 = out + Y_OFF + (rowBase + m * 16 + g) * NYY;
            float* y1 = out + Y_OFF + (rowBase + m * 16 + g + 8) * NYY;
            y0[j0]     = C2[m][i][0] + bp2[j0];
            y0[j0 + 1] = C2[m][i][1] + bp2[j0 + 1];
            y1[j0]     = C2[m][i][2] + bp2[j0];
            y1[j0 + 1] = C2[m][i][3] + bp2[j0 + 1];
        }
}

extern "C" void kernel_launch(void* const* d_in, const int* in_sizes, int n_in,
                              void* d_out, int out_size) {
    int off = (n_in >= 16 && in_sizes[1] == 1) ? 2 : 1;
    const float* Y0  = (const float*)d_in[0];
    const float* Wq  = (const float*)d_in[off + 0];
    const float* bq  = (const float*)d_in[off + 1];
    const float* Wp1 = (const float*)d_in[off + 2];
    const float* bp1 = (const float*)d_in[off + 3];
    const float* Wp2 = (const float*)d_in[off + 4];
    const float* bp2 = (const float*)d_in[off + 5];
    const float* Wl1 = (const float*)d_in[off + 6];
    const float* bl1 = (const float*)d_in[off + 7];
    const float* Wl2 = (const float*)d_in[off + 8];
    const float* bl2 = (const float*)d_in[off + 9];
    const float* Wih = (const float*)d_in[off + 10];
    const float* Whh = (const float*)d_in[off + 11];
    const float* bih = (const float*)d_in[off + 12];
    const float* bhh = (const float*)d_in[off + 13];
    float* out = (float*)d_out;

    cudaFuncSetAttribute(recur_kernel, cudaFuncAttributeMaxDynamicSharedMemorySize,
                         SMEM_UNITS * 4);
    cudaFuncSetAttribute(proj_kernel, cudaFuncAttributeMaxDynamicSharedMemorySize,
                         PROJ_SMEM_UNITS * 4);

    pack_kernel<<<128, 256>>>(Wq, Wl1, Wl2, Wih, Whh, Wp1, Wp2);
    recur_kernel<<<NCTA, 512, SMEM_UNITS * 4>>>(Y0, bq, bl1, bl2, bih, bhh, out);
    proj_kernel<<<(TT * NB) / PROJ_ROWS, 512, PROJ_SMEM_UNITS * 4>>>(bp1, bp2, out);
}